// round 8
// baseline (speedup 1.0000x reference)
#include <cuda_runtime.h>
#include <cuda_bf16.h>
#include <cstdint>

// Problem dims
#define S_ 512
#define B_ 128
#define E_ 100
#define H_ 256
#define T_ 9
#define G_ 1024   // 4*H

// ---------------- scratch (device globals; no allocations) ----------------
__device__ float g_xg[2][S_ * B_ * G_];   // input projections + bias, [dir][s][b][4H]
__device__ float g_hT[2][S_ * H_ * B_];   // hidden states TRANSPOSED [dir][s][unit][batch]
__device__ float g_em[B_ * S_ * T_];      // emissions [b][s][t]
__device__ unsigned g_flagx[2][8][8][32]; // flags [dir][btile][utile], own 128B line

__device__ __forceinline__ float fsig(float x) {
    return __fdividef(1.f, 1.f + __expf(-x));
}
__device__ __forceinline__ float ftanh(float x) {
    return __fdividef(2.f, 1.f + __expf(-2.f * x)) - 1.f;
}

// packed fp32x2 ops (sm_103a)
__device__ __forceinline__ unsigned long long ffma2(unsigned long long a,
                                                    unsigned long long b,
                                                    unsigned long long c) {
    unsigned long long d;
    asm("fma.rn.f32x2 %0, %1, %2, %3;" : "=l"(d) : "l"(a), "l"(b), "l"(c));
    return d;
}
__device__ __forceinline__ unsigned long long addf2(unsigned long long a,
                                                    unsigned long long b) {
    unsigned long long d;
    asm("add.rn.f32x2 %0, %1, %2;" : "=l"(d) : "l"(a), "l"(b));
    return d;
}
__device__ __forceinline__ unsigned long long dup2(float v) {
    unsigned long long d;
    asm("mov.b64 %0, {%1, %1};" : "=l"(d) : "f"(v));
    return d;
}
__device__ __forceinline__ float2 unpack2(unsigned long long v) {
    float2 r;
    asm("mov.b64 {%0, %1}, %2;" : "=f"(r.x), "=f"(r.y) : "l"(v));
    return r;
}
union F4U2 { float4 f4; unsigned long long u2[2]; };

__global__ void reset_kernel() {
    int i = blockIdx.x * blockDim.x + threadIdx.x;
    if (i < 2 * 8 * 8 * 32) ((unsigned*)g_flagx)[i] = 0u;
}

// ---------------- Kernel A: embed gather + input projection --------------
__global__ void xg_kernel(const int* __restrict__ data,
                          const float* __restrict__ emb,
                          const float* __restrict__ Wf,
                          const float* __restrict__ bf,
                          const float* __restrict__ Wb,
                          const float* __restrict__ bb) {
    extern __shared__ float sm[];
    float* Xsm = sm;          // [100][36]
    float* Wsm = sm + 3600;   // [100][132]

    int tt  = blockIdx.x;
    int gt  = blockIdx.y;
    int dir = gt >> 3;
    int g0  = (gt & 7) * 128;
    const float* W    = dir ? Wb : Wf;
    const float* bias = dir ? bb : bf;

    for (int idx = threadIdx.x; idx < 32 * E_; idx += 256) {
        int j = idx / E_, k = idx - j * E_;
        int tok = tt * 32 + j;            // tok = s*128 + b
        int s = tok >> 7, b = tok & 127;
        int row = data[b * S_ + s];
        Xsm[k * 36 + j] = emb[row * E_ + k];
    }
    for (int idx = threadIdx.x; idx < 128 * E_; idx += 256) {
        int r = idx / E_, k = idx - r * E_;
        Wsm[k * 132 + r] = W[(g0 + r) * E_ + k];
    }
    __syncthreads();

    int gg = threadIdx.x & 31;
    int tg = threadIdx.x >> 5;
    float acc[4][4];
#pragma unroll
    for (int i = 0; i < 4; i++)
#pragma unroll
        for (int j = 0; j < 4; j++) acc[i][j] = 0.f;

    const float* wp = &Wsm[gg * 4];
    const float* xp = &Xsm[tg * 4];
    for (int k = 0; k < E_; k++) {
        float4 w = *(const float4*)(wp + k * 132);
        float4 x = *(const float4*)(xp + k * 36);
        acc[0][0] += w.x * x.x; acc[0][1] += w.x * x.y; acc[0][2] += w.x * x.z; acc[0][3] += w.x * x.w;
        acc[1][0] += w.y * x.x; acc[1][1] += w.y * x.y; acc[1][2] += w.y * x.z; acc[1][3] += w.y * x.w;
        acc[2][0] += w.z * x.x; acc[2][1] += w.z * x.y; acc[2][2] += w.z * x.z; acc[2][3] += w.z * x.w;
        acc[3][0] += w.w * x.x; acc[3][1] += w.w * x.y; acc[3][2] += w.w * x.z; acc[3][3] += w.w * x.w;
    }

    float b0v = bias[g0 + gg * 4 + 0];
    float b1v = bias[g0 + gg * 4 + 1];
    float b2v = bias[g0 + gg * 4 + 2];
    float b3v = bias[g0 + gg * 4 + 3];
#pragma unroll
    for (int ti = 0; ti < 4; ti++) {
        int tok = tt * 32 + tg * 4 + ti;
        float4 o = make_float4(acc[0][ti] + b0v, acc[1][ti] + b1v,
                               acc[2][ti] + b2v, acc[3][ti] + b3v);
        *(float4*)&g_xg[dir][tok * G_ + g0 + gg * 4] = o;
    }
}

// ---------------- Kernel B: persistent bidirectional LSTM ----------------
// 128 CTAs x 256 threads. CTA = 32 units x 16 batches, k split 8 ways.
// Thread = (unit-pair up, batch-octet oct, k-chunk kc): register outer
// product 2u x 4g x 8b per k -> 4 LDS.128 feed 32 FFMA2 (crossbar-balanced).
// k-partials reduced by 3-round exchange-split butterfly over kc lanes.
// SMEM: Wsm [256][132] @0 | Hsm [256][20] @33792 | Xsm [2][2048] @38912.
__global__ void __launch_bounds__(256, 1)
lstm_kernel(const float* __restrict__ Whhf, const float* __restrict__ Whhb) {
    extern __shared__ float sm[];
    float* Wsm = sm;            // [k][unit*4+gate], row stride 132 floats
    float* Hsm = sm + 33792;    // [k][16 batches], row stride 20 floats
    float* Xsm = sm + 38912;    // [2][16b][4g][32u]

    int dir   = blockIdx.x >> 6;
    int cid   = blockIdx.x & 63;
    int btile = cid & 7;            // 8 batch tiles of 16
    int utile = cid >> 3;           // 8 unit tiles of 32
    int b0    = btile * 16;
    int u0    = utile * 32;
    const float* Whh = dir ? Whhb : Whhf;

    // stage W slice: [k][unit*4+gate] for unit<32, gate<4
    for (int idx = threadIdx.x; idx < 128 * 256; idx += 256) {
        int r = idx >> 8, k = idx & 255;
        int unit = r >> 2, gate = r & 3;
        Wsm[k * 132 + unit * 4 + gate] = Whh[(gate * 256 + u0 + unit) * 256 + k];
    }

    int lane = threadIdx.x & 31;
    int w    = threadIdx.x >> 5;            // warp 0..7
    int kc   = lane & 7;                    // k-chunk 0..7
    int oct  = (lane >> 3) & 1;             // batch octet 0..1
    int upl  = lane >> 4;                   // unit-pair low bit
    int up   = upl + 2 * w;                 // unit-pair 0..15

    const float* wp = &Wsm[kc * 32 * 132 + up * 8];
    const float* hp = &Hsm[kc * 32 * 20 + oct * 8];

    // this lane's epilogue cells: unit ucell, batches bcell, bcell+1
    int usel  = kc >> 2;
    int bp    = kc & 3;
    int ucell = u0 + up * 2 + usel;
    int bcell = b0 + oct * 8 + bp * 2;
    int xbase = (oct * 8 + bp * 2) * 128 + (up * 2 + usel);  // Xsm[b][g][u] idx (gate stride 32)
    float cE = 0.f, cO = 0.f;

    __syncthreads();   // W staged

    for (int ts = 0; ts < S_; ts++) {
        int t = dir ? (S_ - 1 - ts) : ts;
        int xbuf = ts & 1;

        // stage xg tile (coalesced, independent of flag-gated h)
        {
            const float* src = &g_xg[dir][(t * B_ + b0) * G_ + u0];
            float* dst = &Xsm[xbuf * 2048];
#pragma unroll
            for (int it = 0; it < 2; it++) {
                int idx = threadIdx.x + it * 256;      // 0..511 float4 moves
                int reg = idx >> 3, fq = idx & 7;      // reg = b*4+gate
                float4 v = *(const float4*)&src[(reg >> 2) * G_ + (reg & 3) * 256 + fq * 4];
                *(float4*)&dst[reg * 32 + fq * 4] = v;
            }
        }

        unsigned long long A[8][4];
#pragma unroll
        for (int g = 0; g < 8; g++)
#pragma unroll
            for (int j = 0; j < 4; j++) A[g][j] = 0ull;

        if (ts > 0) {
            // wait for the 8 CTAs of this (dir,btile) group: step ts-1 done
            if (threadIdx.x < 8) {
                volatile unsigned* fr = &g_flagx[dir][btile][threadIdx.x][0];
                unsigned v;
                do { v = *fr; } while (!__all_sync(0xFFu, v >= (unsigned)ts));
                __threadfence();
            }
            __syncthreads();

            int tp = dir ? (t + 1) : (t - 1);
            // stage h_prev [256 units][16 batches] compact
            const float* hprev = &g_hT[dir][(tp * H_) * B_];
#pragma unroll
            for (int it = 0; it < 4; it++) {
                int idx = threadIdx.x + it * 256;      // 0..1023 float4 moves
                int k = idx >> 2, q = idx & 3;
                float4 hv = *(const float4*)&hprev[k * B_ + b0 + q * 4];
                *(float4*)&Hsm[k * 20 + q * 4] = hv;
            }
            __syncthreads();

            // k-loop over this thread's 32-k chunk
#pragma unroll 4
            for (int kk = 0; kk < 32; kk++) {
                F4U2 wA; wA.f4 = *(const float4*)(wp + kk * 132);      // unit0 (wi,wf,wg,wo)
                F4U2 wB; wB.f4 = *(const float4*)(wp + kk * 132 + 4);  // unit1
                float4 hL = *(const float4*)(hp + kk * 20);            // b0..b3
                float4 hH = *(const float4*)(hp + kk * 20 + 4);        // b4..b7
                unsigned long long hd[8];
                hd[0] = dup2(hL.x); hd[1] = dup2(hL.y);
                hd[2] = dup2(hL.z); hd[3] = dup2(hL.w);
                hd[4] = dup2(hH.x); hd[5] = dup2(hH.y);
                hd[6] = dup2(hH.z); hd[7] = dup2(hH.w);
#pragma unroll
                for (int g = 0; g < 8; g++) {
                    unsigned long long wif = (g >> 2) ? wB.u2[0] : wA.u2[0];
                    unsigned long long wgo = (g >> 2) ? wB.u2[1] : wA.u2[1];
                    int be = (g & 3) * 2;
                    A[g][0] = ffma2(wif, hd[be],     A[g][0]);
                    A[g][1] = ffma2(wif, hd[be + 1], A[g][1]);
                    A[g][2] = ffma2(wgo, hd[be],     A[g][2]);
                    A[g][3] = ffma2(wgo, hd[be + 1], A[g][3]);
                }
            }
        } else {
            __syncthreads();   // order Xsm staging before epilogue reads
        }

        // ---- exchange-split butterfly over kc lanes (masks 1,2,4) ----
        unsigned long long Bx[4][4], Cx[2][4], D[4];
#pragma unroll
        for (int q = 0; q < 4; q++) {
            int gl = q * 2, gh = gl + 1;
#pragma unroll
            for (int j = 0; j < 4; j++) {
                unsigned long long s = (kc & 1) ? A[gl][j] : A[gh][j];
                unsigned long long r = __shfl_xor_sync(0xFFFFFFFFu, s, 1);
                unsigned long long kpt = (kc & 1) ? A[gh][j] : A[gl][j];
                Bx[q][j] = addf2(kpt, r);
            }
        }
#pragma unroll
        for (int q = 0; q < 2; q++) {
            int gl = q * 2, gh = gl + 1;
#pragma unroll
            for (int j = 0; j < 4; j++) {
                unsigned long long s = (kc & 2) ? Bx[gl][j] : Bx[gh][j];
                unsigned long long r = __shfl_xor_sync(0xFFFFFFFFu, s, 2);
                unsigned long long kpt = (kc & 2) ? Bx[gh][j] : Bx[gl][j];
                Cx[q][j] = addf2(kpt, r);
            }
        }
#pragma unroll
        for (int j = 0; j < 4; j++) {
            unsigned long long s = (kc & 4) ? Cx[0][j] : Cx[1][j];
            unsigned long long r = __shfl_xor_sync(0xFFFFFFFFu, s, 4);
            unsigned long long kpt = (kc & 4) ? Cx[1][j] : Cx[0][j];
            D[j] = addf2(kpt, r);
        }

        // ---- epilogue: 2 cells per lane ----
        const float* xv = &Xsm[xbuf * 2048 + xbase];
        float2 ife = unpack2(D[0]), ifo = unpack2(D[1]);
        float2 goe = unpack2(D[2]), goo = unpack2(D[3]);

        float aiE = ife.x + xv[0 * 32], afE = ife.y + xv[1 * 32];
        float agE = goe.x + xv[2 * 32], aoE = goe.y + xv[3 * 32];
        cE = fsig(afE) * cE + fsig(aiE) * ftanh(agE);
        float hE = fsig(aoE) * ftanh(cE);

        float aiO = ifo.x + xv[128 + 0 * 32], afO = ifo.y + xv[128 + 1 * 32];
        float agO = goo.x + xv[128 + 2 * 32], aoO = goo.y + xv[128 + 3 * 32];
        cO = fsig(afO) * cO + fsig(aiO) * ftanh(agO);
        float hO = fsig(aoO) * ftanh(cO);

        *(float2*)&g_hT[dir][(t * H_ + ucell) * B_ + bcell] = make_float2(hE, hO);

        // release: fence-all, barrier, publish
        __threadfence();
        __syncthreads();
        if (threadIdx.x == 0)
            *(volatile unsigned*)&g_flagx[dir][btile][utile][0] = (unsigned)(ts + 1);
    }
}

// ---------------- Kernel C: MLP emissions (transposed h layout) ----------
__global__ void mlp_kernel(const float* __restrict__ mlpW,
                           const float* __restrict__ mlpb) {
    __shared__ float Wsm[T_ * 2 * H_];
    for (int i = threadIdx.x; i < T_ * 2 * H_; i += 128) Wsm[i] = mlpW[i];
    __syncthreads();

    int s = blockIdx.x;
    int b = threadIdx.x;

    float acc[T_];
#pragma unroll
    for (int t = 0; t < T_; t++) acc[t] = 0.f;

    const float* hf = &g_hT[0][(s * H_) * B_ + b];
    const float* hb = &g_hT[1][(s * H_) * B_ + b];
#pragma unroll 4
    for (int k = 0; k < H_; k++) {
        float v1 = hf[k * B_];
        float v2 = hb[k * B_];
#pragma unroll
        for (int t = 0; t < T_; t++) {
            acc[t] += v1 * Wsm[t * 512 + k];
            acc[t] += v2 * Wsm[t * 512 + 256 + k];
        }
    }
#pragma unroll
    for (int t = 0; t < T_; t++)
        g_em[(b * S_ + s) * T_ + t] = acc[t] + mlpb[t];
}

// ---------------- Kernel D: CRF Viterbi (one warp per batch) -------------
__global__ void viterbi_kernel(const int* __restrict__ data,
                               const float* __restrict__ stt,
                               const float* __restrict__ trn,
                               const float* __restrict__ ett,
                               float* __restrict__ out) {
    __shared__ int sbp[2][S_][10];
    int w = threadIdx.x >> 5, lane = threadIdx.x & 31;
    int b = blockIdx.x * 2 + w;
    int cc = lane < T_ ? lane : (T_ - 1);

    int cnt = 0;
    for (int s = lane; s < S_; s += 32) cnt += (data[b * S_ + s] != 0);
    for (int off = 16; off; off >>= 1) cnt += __shfl_xor_sync(0xFFFFFFFFu, cnt, off);
    int len = cnt;

    float tr[T_];
#pragma unroll
    for (int p = 0; p < T_; p++) tr[p] = trn[p * T_ + cc];

    float score = stt[cc] + g_em[(b * S_ + 0) * T_ + cc];
    float e_next = g_em[(b * S_ + 1) * T_ + cc];

    for (int t = 1; t < S_; t++) {
        float e = e_next;
        if (t + 1 < S_) e_next = g_em[(b * S_ + t + 1) * T_ + cc];  // prefetch
        float best = -1e30f; int bp = 0;
#pragma unroll
        for (int p = 0; p < T_; p++) {
            float sp = __shfl_sync(0xFFFFFFFFu, score, p);
            float cand = sp + tr[p] + e;
            if (cand > best) { best = cand; bp = p; }   // first-max tie-break
        }
        if (lane < T_) sbp[w][t][lane] = bp;
        if (t < len) score = best;
    }

    float fin = score + ett[cc];
    float bestf = -1e30f; int tag = 0;
#pragma unroll
    for (int p = 0; p < T_; p++) {
        float v = __shfl_sync(0xFFFFFFFFu, fin, p);
        if (v > bestf) { bestf = v; tag = p; }
    }
    if (lane == 0) out[B_ * S_ + b] = bestf;

    if (lane == 0) out[b * S_ + (S_ - 1)] = ((S_ - 1) < len) ? (float)tag : 0.f;
    for (int s2 = S_ - 2; s2 >= 0; s2--) {
        int bpv = sbp[w][s2 + 1][cc];
        int prev = __shfl_sync(0xFFFFFFFFu, bpv, tag);
        if (s2 + 1 < len) tag = prev;
        if (lane == 0) out[b * S_ + s2] = (s2 < len) ? (float)tag : 0.f;
    }
}

// ---------------- launch ----------------
extern "C" void kernel_launch(void* const* d_in, const int* in_sizes, int n_in,
                              void* d_out, int out_size) {
    const int*   data = (const int*)d_in[0];
    // d_in[1] = mask (ignored; mask == (data != 0))
    const float* emb  = (const float*)d_in[2];
    const float* Wihf = (const float*)d_in[3];
    const float* Whhf = (const float*)d_in[4];
    const float* bf   = (const float*)d_in[5];
    const float* Wihb = (const float*)d_in[6];
    const float* Whhb = (const float*)d_in[7];
    const float* bb   = (const float*)d_in[8];
    const float* mlpW = (const float*)d_in[9];
    const float* mlpb = (const float*)d_in[10];
    const float* stt  = (const float*)d_in[11];
    const float* trn  = (const float*)d_in[12];
    const float* ett  = (const float*)d_in[13];
    float* out = (float*)d_out;

    cudaFuncSetAttribute(xg_kernel,   cudaFuncAttributeMaxDynamicSharedMemorySize, 67200);
    cudaFuncSetAttribute(lstm_kernel, cudaFuncAttributeMaxDynamicSharedMemorySize, 172032);

    reset_kernel<<<8, 512>>>();
    dim3 gA(2048, 16);
    xg_kernel<<<gA, 256, 67200>>>(data, emb, Wihf, bf, Wihb, bb);
    lstm_kernel<<<128, 256, 172032>>>(Whhf, Whhb);
    mlp_kernel<<<512, 128>>>(mlpW, mlpb);
    viterbi_kernel<<<64, 64>>>(data, stt, trn, ett, out);
}

// round 9
// speedup vs baseline: 1.7027x; 1.7027x over previous
#include <cuda_runtime.h>
#include <cuda_bf16.h>
#include <cstdint>

// Problem dims
#define S_ 512
#define B_ 128
#define E_ 100
#define H_ 256
#define T_ 9
#define G_ 1024   // 4*H

// ---------------- scratch (device globals; no allocations) ----------------
__device__ float g_xg[2][S_ * B_ * G_];   // input projections + bias, [dir][s][b][4H]
__device__ float g_hT[2][S_ * H_ * B_];   // hidden states TRANSPOSED [dir][s][unit][batch]
__device__ float g_em[B_ * S_ * T_];      // emissions [b][s][t]
__device__ unsigned g_flagx[2][8][8][32]; // flags [dir][btile][utile], own 128B line

__device__ __forceinline__ float fsig(float x) {
    return __fdividef(1.f, 1.f + __expf(-x));
}
__device__ __forceinline__ float ftanh(float x) {
    return __fdividef(2.f, 1.f + __expf(-2.f * x)) - 1.f;
}

// packed fp32x2 ops (sm_103a)
__device__ __forceinline__ unsigned long long ffma2(unsigned long long a,
                                                    unsigned long long b,
                                                    unsigned long long c) {
    unsigned long long d;
    asm("fma.rn.f32x2 %0, %1, %2, %3;" : "=l"(d) : "l"(a), "l"(b), "l"(c));
    return d;
}
__device__ __forceinline__ unsigned long long addf2(unsigned long long a,
                                                    unsigned long long b) {
    unsigned long long d;
    asm("add.rn.f32x2 %0, %1, %2;" : "=l"(d) : "l"(a), "l"(b));
    return d;
}
__device__ __forceinline__ unsigned long long dup2(float v) {
    unsigned long long d;
    asm("mov.b64 %0, {%1, %1};" : "=l"(d) : "f"(v));
    return d;
}
__device__ __forceinline__ float2 unpack2(unsigned long long v) {
    float2 r;
    asm("mov.b64 {%0, %1}, %2;" : "=f"(r.x), "=f"(r.y) : "l"(v));
    return r;
}
union F4U2 { float4 f4; unsigned long long u2[2]; };

__global__ void reset_kernel() {
    int i = blockIdx.x * blockDim.x + threadIdx.x;
    if (i < 2 * 8 * 8 * 32) ((unsigned*)g_flagx)[i] = 0u;
}

// ---------------- Kernel A: embed gather + input projection --------------
__global__ void xg_kernel(const int* __restrict__ data,
                          const float* __restrict__ emb,
                          const float* __restrict__ Wf,
                          const float* __restrict__ bf,
                          const float* __restrict__ Wb,
                          const float* __restrict__ bb) {
    extern __shared__ float sm[];
    float* Xsm = sm;          // [100][36]
    float* Wsm = sm + 3600;   // [100][132]

    int tt  = blockIdx.x;
    int gt  = blockIdx.y;
    int dir = gt >> 3;
    int g0  = (gt & 7) * 128;
    const float* W    = dir ? Wb : Wf;
    const float* bias = dir ? bb : bf;

    for (int idx = threadIdx.x; idx < 32 * E_; idx += 256) {
        int j = idx / E_, k = idx - j * E_;
        int tok = tt * 32 + j;            // tok = s*128 + b
        int s = tok >> 7, b = tok & 127;
        int row = data[b * S_ + s];
        Xsm[k * 36 + j] = emb[row * E_ + k];
    }
    for (int idx = threadIdx.x; idx < 128 * E_; idx += 256) {
        int r = idx / E_, k = idx - r * E_;
        Wsm[k * 132 + r] = W[(g0 + r) * E_ + k];
    }
    __syncthreads();

    int gg = threadIdx.x & 31;
    int tg = threadIdx.x >> 5;
    float acc[4][4];
#pragma unroll
    for (int i = 0; i < 4; i++)
#pragma unroll
        for (int j = 0; j < 4; j++) acc[i][j] = 0.f;

    const float* wp = &Wsm[gg * 4];
    const float* xp = &Xsm[tg * 4];
    for (int k = 0; k < E_; k++) {
        float4 w = *(const float4*)(wp + k * 132);
        float4 x = *(const float4*)(xp + k * 36);
        acc[0][0] += w.x * x.x; acc[0][1] += w.x * x.y; acc[0][2] += w.x * x.z; acc[0][3] += w.x * x.w;
        acc[1][0] += w.y * x.x; acc[1][1] += w.y * x.y; acc[1][2] += w.y * x.z; acc[1][3] += w.y * x.w;
        acc[2][0] += w.z * x.x; acc[2][1] += w.z * x.y; acc[2][2] += w.z * x.z; acc[2][3] += w.z * x.w;
        acc[3][0] += w.w * x.x; acc[3][1] += w.w * x.y; acc[3][2] += w.w * x.z; acc[3][3] += w.w * x.w;
    }

    float b0v = bias[g0 + gg * 4 + 0];
    float b1v = bias[g0 + gg * 4 + 1];
    float b2v = bias[g0 + gg * 4 + 2];
    float b3v = bias[g0 + gg * 4 + 3];
#pragma unroll
    for (int ti = 0; ti < 4; ti++) {
        int tok = tt * 32 + tg * 4 + ti;
        float4 o = make_float4(acc[0][ti] + b0v, acc[1][ti] + b1v,
                               acc[2][ti] + b2v, acc[3][ti] + b3v);
        *(float4*)&g_xg[dir][tok * G_ + g0 + gg * 4] = o;
    }
}

// ---------------- Kernel B: persistent bidirectional LSTM ----------------
// 128 CTAs x 256 threads. CTA = 32 units x 16 batches, k split 8 ways.
// Thread = (unit-pair up, batch-octet oct, k-chunk kc): register outer
// product 2u x 4g x 8b per k -> 4 LDS.128 feed 32 FFMA2 (1 B/MAC).
// k-swizzled CONFLICT-FREE layouts:
//   Wsm[kk][kc][132]: addr = kk*1056 + kc*132 + row   (kc -> bank quad 132%32=4*kc: all 8 quads)
//   Hsm[kk][kc][20]:  addr = kk*160  + kc*20  + b     (kc -> quad 5*kc mod 8: all 8 quads)
// k-partials reduced by 3-round exchange-split butterfly over kc lanes.
// SMEM: Wsm 32*1056 fl @0 | Hsm 32*160 fl @33792 | Xsm [2][2048] @38912.
__global__ void __launch_bounds__(256, 1)
lstm_kernel(const float* __restrict__ Whhf, const float* __restrict__ Whhb) {
    extern __shared__ float sm[];
    float* Wsm = sm;            // [32][8][132]
    float* Hsm = sm + 33792;    // [32][8][20]
    float* Xsm = sm + 38912;    // [2][16b][4g][32u]

    int dir   = blockIdx.x >> 6;
    int cid   = blockIdx.x & 63;
    int btile = cid & 7;            // 8 batch tiles of 16
    int utile = cid >> 3;           // 8 unit tiles of 32
    int b0    = btile * 16;
    int u0    = utile * 32;
    const float* Whh = dir ? Whhb : Whhf;

    // stage W slice: [kk][kc][row] for row = unit*4+gate, unit<32, gate<4
    for (int idx = threadIdx.x; idx < 128 * 256; idx += 256) {
        int r = idx >> 8, k = idx & 255;
        int unit = r >> 2, gate = r & 3;
        Wsm[(k & 31) * 1056 + (k >> 5) * 132 + unit * 4 + gate] =
            Whh[(gate * 256 + u0 + unit) * 256 + k];
    }

    int lane = threadIdx.x & 31;
    int w    = threadIdx.x >> 5;            // warp 0..7
    int kc   = lane & 7;                    // k-chunk 0..7
    int oct  = (lane >> 3) & 1;             // batch octet 0..1
    int upl  = lane >> 4;                   // unit-pair low bit
    int up   = upl + 2 * w;                 // unit-pair 0..15

    const float* wp = &Wsm[kc * 132 + up * 8];
    const float* hp = &Hsm[kc * 20 + oct * 8];

    // this lane's epilogue cells: unit ucell, batches bcell, bcell+1
    int usel  = kc >> 2;
    int bp    = kc & 3;
    int ucell = u0 + up * 2 + usel;
    int bcell = b0 + oct * 8 + bp * 2;
    int xbase = (oct * 8 + bp * 2) * 128 + (up * 2 + usel);  // Xsm[b][g][u] idx (gate stride 32)
    float cE = 0.f, cO = 0.f;

    __syncthreads();   // W staged

    for (int ts = 0; ts < S_; ts++) {
        int t = dir ? (S_ - 1 - ts) : ts;
        int xbuf = ts & 1;

        // stage xg tile (coalesced, independent of flag-gated h)
        {
            const float* src = &g_xg[dir][(t * B_ + b0) * G_ + u0];
            float* dst = &Xsm[xbuf * 2048];
#pragma unroll
            for (int it = 0; it < 2; it++) {
                int idx = threadIdx.x + it * 256;      // 0..511 float4 moves
                int reg = idx >> 3, fq = idx & 7;      // reg = b*4+gate
                float4 v = *(const float4*)&src[(reg >> 2) * G_ + (reg & 3) * 256 + fq * 4];
                *(float4*)&dst[reg * 32 + fq * 4] = v;
            }
        }

        unsigned long long A[8][4];
#pragma unroll
        for (int g = 0; g < 8; g++)
#pragma unroll
            for (int j = 0; j < 4; j++) A[g][j] = 0ull;

        if (ts > 0) {
            // wait for the 8 CTAs of this (dir,btile) group: step ts-1 done
            if (threadIdx.x < 8) {
                volatile unsigned* fr = &g_flagx[dir][btile][threadIdx.x][0];
                unsigned v;
                do { v = *fr; } while (!__all_sync(0xFFu, v >= (unsigned)ts));
                __threadfence();
            }
            __syncthreads();

            int tp = dir ? (t + 1) : (t - 1);
            // stage h_prev [256 units][16 batches] -> swizzled [kk][kc][20]
            const float* hprev = &g_hT[dir][(tp * H_) * B_];
#pragma unroll
            for (int it = 0; it < 4; it++) {
                int idx = threadIdx.x + it * 256;      // 0..1023 float4 moves
                int k = idx >> 2, q = idx & 3;
                float4 hv = *(const float4*)&hprev[k * B_ + b0 + q * 4];
                *(float4*)&Hsm[(k & 31) * 160 + (k >> 5) * 20 + q * 4] = hv;
            }
            __syncthreads();

            // k-loop over this thread's 32-k chunk (stride: kk -> +1056 W, +160 H)
#pragma unroll 4
            for (int kk = 0; kk < 32; kk++) {
                F4U2 wA; wA.f4 = *(const float4*)(wp + kk * 1056);      // unit0 (wi,wf,wg,wo)
                F4U2 wB; wB.f4 = *(const float4*)(wp + kk * 1056 + 4);  // unit1
                float4 hL = *(const float4*)(hp + kk * 160);            // b0..b3
                float4 hH = *(const float4*)(hp + kk * 160 + 4);        // b4..b7
                unsigned long long hd[8];
                hd[0] = dup2(hL.x); hd[1] = dup2(hL.y);
                hd[2] = dup2(hL.z); hd[3] = dup2(hL.w);
                hd[4] = dup2(hH.x); hd[5] = dup2(hH.y);
                hd[6] = dup2(hH.z); hd[7] = dup2(hH.w);
#pragma unroll
                for (int g = 0; g < 8; g++) {
                    unsigned long long wif = (g >> 2) ? wB.u2[0] : wA.u2[0];
                    unsigned long long wgo = (g >> 2) ? wB.u2[1] : wA.u2[1];
                    int be = (g & 3) * 2;
                    A[g][0] = ffma2(wif, hd[be],     A[g][0]);
                    A[g][1] = ffma2(wif, hd[be + 1], A[g][1]);
                    A[g][2] = ffma2(wgo, hd[be],     A[g][2]);
                    A[g][3] = ffma2(wgo, hd[be + 1], A[g][3]);
                }
            }
        } else {
            __syncthreads();   // order Xsm staging before epilogue reads
        }

        // ---- exchange-split butterfly over kc lanes (masks 1,2,4) ----
        unsigned long long Bx[4][4], Cx[2][4], D[4];
#pragma unroll
        for (int q = 0; q < 4; q++) {
            int gl = q * 2, gh = gl + 1;
#pragma unroll
            for (int j = 0; j < 4; j++) {
                unsigned long long s = (kc & 1) ? A[gl][j] : A[gh][j];
                unsigned long long r = __shfl_xor_sync(0xFFFFFFFFu, s, 1);
                unsigned long long kpt = (kc & 1) ? A[gh][j] : A[gl][j];
                Bx[q][j] = addf2(kpt, r);
            }
        }
#pragma unroll
        for (int q = 0; q < 2; q++) {
            int gl = q * 2, gh = gl + 1;
#pragma unroll
            for (int j = 0; j < 4; j++) {
                unsigned long long s = (kc & 2) ? Bx[gl][j] : Bx[gh][j];
                unsigned long long r = __shfl_xor_sync(0xFFFFFFFFu, s, 2);
                unsigned long long kpt = (kc & 2) ? Bx[gh][j] : Bx[gl][j];
                Cx[q][j] = addf2(kpt, r);
            }
        }
#pragma unroll
        for (int j = 0; j < 4; j++) {
            unsigned long long s = (kc & 4) ? Cx[0][j] : Cx[1][j];
            unsigned long long r = __shfl_xor_sync(0xFFFFFFFFu, s, 4);
            unsigned long long kpt = (kc & 4) ? Cx[1][j] : Cx[0][j];
            D[j] = addf2(kpt, r);
        }

        // ---- epilogue: 2 cells per lane ----
        const float* xv = &Xsm[xbuf * 2048 + xbase];
        float2 ife = unpack2(D[0]), ifo = unpack2(D[1]);
        float2 goe = unpack2(D[2]), goo = unpack2(D[3]);

        float aiE = ife.x + xv[0 * 32], afE = ife.y + xv[1 * 32];
        float agE = goe.x + xv[2 * 32], aoE = goe.y + xv[3 * 32];
        cE = fsig(afE) * cE + fsig(aiE) * ftanh(agE);
        float hE = fsig(aoE) * ftanh(cE);

        float aiO = ifo.x + xv[128 + 0 * 32], afO = ifo.y + xv[128 + 1 * 32];
        float agO = goo.x + xv[128 + 2 * 32], aoO = goo.y + xv[128 + 3 * 32];
        cO = fsig(afO) * cO + fsig(aiO) * ftanh(agO);
        float hO = fsig(aoO) * ftanh(cO);

        *(float2*)&g_hT[dir][(t * H_ + ucell) * B_ + bcell] = make_float2(hE, hO);

        // release: fence-all, barrier, publish
        __threadfence();
        __syncthreads();
        if (threadIdx.x == 0)
            *(volatile unsigned*)&g_flagx[dir][btile][utile][0] = (unsigned)(ts + 1);
    }
}

// ---------------- Kernel C: MLP emissions (transposed h layout) ----------
__global__ void mlp_kernel(const float* __restrict__ mlpW,
                           const float* __restrict__ mlpb) {
    __shared__ float Wsm[T_ * 2 * H_];
    for (int i = threadIdx.x; i < T_ * 2 * H_; i += 128) Wsm[i] = mlpW[i];
    __syncthreads();

    int s = blockIdx.x;
    int b = threadIdx.x;

    float acc[T_];
#pragma unroll
    for (int t = 0; t < T_; t++) acc[t] = 0.f;

    const float* hf = &g_hT[0][(s * H_) * B_ + b];
    const float* hb = &g_hT[1][(s * H_) * B_ + b];
#pragma unroll 4
    for (int k = 0; k < H_; k++) {
        float v1 = hf[k * B_];
        float v2 = hb[k * B_];
#pragma unroll
        for (int t = 0; t < T_; t++) {
            acc[t] += v1 * Wsm[t * 512 + k];
            acc[t] += v2 * Wsm[t * 512 + 256 + k];
        }
    }
#pragma unroll
    for (int t = 0; t < T_; t++)
        g_em[(b * S_ + s) * T_ + t] = acc[t] + mlpb[t];
}

// ---------------- Kernel D: CRF Viterbi (one warp per batch) -------------
__global__ void viterbi_kernel(const int* __restrict__ data,
                               const float* __restrict__ stt,
                               const float* __restrict__ trn,
                               const float* __restrict__ ett,
                               float* __restrict__ out) {
    __shared__ int sbp[2][S_][10];
    int w = threadIdx.x >> 5, lane = threadIdx.x & 31;
    int b = blockIdx.x * 2 + w;
    int cc = lane < T_ ? lane : (T_ - 1);

    int cnt = 0;
    for (int s = lane; s < S_; s += 32) cnt += (data[b * S_ + s] != 0);
    for (int off = 16; off; off >>= 1) cnt += __shfl_xor_sync(0xFFFFFFFFu, cnt, off);
    int len = cnt;

    float tr[T_];
#pragma unroll
    for (int p = 0; p < T_; p++) tr[p] = trn[p * T_ + cc];

    float score = stt[cc] + g_em[(b * S_ + 0) * T_ + cc];
    float e_next = g_em[(b * S_ + 1) * T_ + cc];

    for (int t = 1; t < S_; t++) {
        float e = e_next;
        if (t + 1 < S_) e_next = g_em[(b * S_ + t + 1) * T_ + cc];  // prefetch
        float best = -1e30f; int bp = 0;
#pragma unroll
        for (int p = 0; p < T_; p++) {
            float sp = __shfl_sync(0xFFFFFFFFu, score, p);
            float cand = sp + tr[p] + e;
            if (cand > best) { best = cand; bp = p; }   // first-max tie-break
        }
        if (lane < T_) sbp[w][t][lane] = bp;
        if (t < len) score = best;
    }

    float fin = score + ett[cc];
    float bestf = -1e30f; int tag = 0;
#pragma unroll
    for (int p = 0; p < T_; p++) {
        float v = __shfl_sync(0xFFFFFFFFu, fin, p);
        if (v > bestf) { bestf = v; tag = p; }
    }
    if (lane == 0) out[B_ * S_ + b] = bestf;

    if (lane == 0) out[b * S_ + (S_ - 1)] = ((S_ - 1) < len) ? (float)tag : 0.f;
    for (int s2 = S_ - 2; s2 >= 0; s2--) {
        int bpv = sbp[w][s2 + 1][cc];
        int prev = __shfl_sync(0xFFFFFFFFu, bpv, tag);
        if (s2 + 1 < len) tag = prev;
        if (lane == 0) out[b * S_ + s2] = (s2 < len) ? (float)tag : 0.f;
    }
}

// ---------------- launch ----------------
extern "C" void kernel_launch(void* const* d_in, const int* in_sizes, int n_in,
                              void* d_out, int out_size) {
    const int*   data = (const int*)d_in[0];
    // d_in[1] = mask (ignored; mask == (data != 0))
    const float* emb  = (const float*)d_in[2];
    const float* Wihf = (const float*)d_in[3];
    const float* Whhf = (const float*)d_in[4];
    const float* bf   = (const float*)d_in[5];
    const float* Wihb = (const float*)d_in[6];
    const float* Whhb = (const float*)d_in[7];
    const float* bb   = (const float*)d_in[8];
    const float* mlpW = (const float*)d_in[9];
    const float* mlpb = (const float*)d_in[10];
    const float* stt  = (const float*)d_in[11];
    const float* trn  = (const float*)d_in[12];
    const float* ett  = (const float*)d_in[13];
    float* out = (float*)d_out;

    cudaFuncSetAttribute(xg_kernel,   cudaFuncAttributeMaxDynamicSharedMemorySize, 67200);
    cudaFuncSetAttribute(lstm_kernel, cudaFuncAttributeMaxDynamicSharedMemorySize, 172032);

    reset_kernel<<<8, 512>>>();
    dim3 gA(2048, 16);
    xg_kernel<<<gA, 256, 67200>>>(data, emb, Wihf, bf, Wihb, bb);
    lstm_kernel<<<128, 256, 172032>>>(Whhf, Whhb);
    mlp_kernel<<<512, 128>>>(mlpW, mlpb);
    viterbi_kernel<<<64, 64>>>(data, stt, trn, ett, out);
}

// round 12
// speedup vs baseline: 2.4605x; 1.4451x over previous
#include <cuda_runtime.h>
#include <cuda_bf16.h>
#include <cstdint>

// Problem dims
#define S_ 512
#define B_ 128
#define E_ 100
#define H_ 256
#define T_ 9
#define G_ 1024   // 4*H

// ---------------- scratch (device globals; no allocations) ----------------
__device__ float g_xg[2][S_ * B_ * G_];          // input proj + bias [dir][s][b][4H]
__device__ __nv_bfloat16 g_h3[2][S_][3][B_][H_]; // h 3-plane bf16 split
__device__ float g_em[B_ * S_ * T_];             // emissions [b][s][t]
__device__ unsigned g_flagx[2][4][16][32];       // flags [dir][btile][utile], own 128B line

__device__ __forceinline__ float fsig(float x) {
    return __fdividef(1.f, 1.f + __expf(-x));
}
__device__ __forceinline__ float ftanh(float x) {
    return __fdividef(2.f, 1.f + __expf(-2.f * x)) - 1.f;
}

__device__ __forceinline__ uint32_t smem_u32(const void* p) {
    uint32_t a;
    asm("{ .reg .u64 t; cvta.to.shared.u64 t, %1; cvt.u32.u64 %0, t; }"
        : "=r"(a) : "l"(p));
    return a;
}

#define LDMX4(r, addr) \
    asm volatile("ldmatrix.sync.aligned.m8n8.x4.shared.b16 {%0,%1,%2,%3}, [%4];" \
        : "=r"((r)[0]), "=r"((r)[1]), "=r"((r)[2]), "=r"((r)[3]) : "r"(addr))

__device__ __forceinline__ void mma16816(float* d, const uint32_t* a, const uint32_t* b) {
    asm volatile(
        "mma.sync.aligned.m16n8k16.row.col.f32.bf16.bf16.f32 "
        "{%0,%1,%2,%3}, {%4,%5,%6,%7}, {%8,%9}, {%0,%1,%2,%3};"
        : "+f"(d[0]), "+f"(d[1]), "+f"(d[2]), "+f"(d[3])
        : "r"(a[0]), "r"(a[1]), "r"(a[2]), "r"(a[3]), "r"(b[0]), "r"(b[1]));
}

__global__ void reset_kernel() {
    int i = blockIdx.x * blockDim.x + threadIdx.x;
    if (i < 2 * 4 * 16 * 32) ((unsigned*)g_flagx)[i] = 0u;
}

// ---------------- Kernel A: embed gather + input projection --------------
__global__ void xg_kernel(const int* __restrict__ data,
                          const float* __restrict__ emb,
                          const float* __restrict__ Wf,
                          const float* __restrict__ bf,
                          const float* __restrict__ Wb,
                          const float* __restrict__ bb) {
    extern __shared__ float sm[];
    float* Xsm = sm;          // [100][36]
    float* Wsm = sm + 3600;   // [100][132]

    int tt  = blockIdx.x;
    int gt  = blockIdx.y;
    int dir = gt >> 3;
    int g0  = (gt & 7) * 128;
    const float* W    = dir ? Wb : Wf;
    const float* bias = dir ? bb : bf;

    for (int idx = threadIdx.x; idx < 32 * E_; idx += 256) {
        int j = idx / E_, k = idx - j * E_;
        int tok = tt * 32 + j;            // tok = s*128 + b
        int s = tok >> 7, b = tok & 127;
        int row = data[b * S_ + s];
        Xsm[k * 36 + j] = emb[row * E_ + k];
    }
    for (int idx = threadIdx.x; idx < 128 * E_; idx += 256) {
        int r = idx / E_, k = idx - r * E_;
        Wsm[k * 132 + r] = W[(g0 + r) * E_ + k];
    }
    __syncthreads();

    int gg = threadIdx.x & 31;
    int tg = threadIdx.x >> 5;
    float acc[4][4];
#pragma unroll
    for (int i = 0; i < 4; i++)
#pragma unroll
        for (int j = 0; j < 4; j++) acc[i][j] = 0.f;

    const float* wp = &Wsm[gg * 4];
    const float* xp = &Xsm[tg * 4];
    for (int k = 0; k < E_; k++) {
        float4 w = *(const float4*)(wp + k * 132);
        float4 x = *(const float4*)(xp + k * 36);
        acc[0][0] += w.x * x.x; acc[0][1] += w.x * x.y; acc[0][2] += w.x * x.z; acc[0][3] += w.x * x.w;
        acc[1][0] += w.y * x.x; acc[1][1] += w.y * x.y; acc[1][2] += w.y * x.z; acc[1][3] += w.y * x.w;
        acc[2][0] += w.z * x.x; acc[2][1] += w.z * x.y; acc[2][2] += w.z * x.z; acc[2][3] += w.z * x.w;
        acc[3][0] += w.w * x.x; acc[3][1] += w.w * x.y; acc[3][2] += w.w * x.z; acc[3][3] += w.w * x.w;
    }

    float b0v = bias[g0 + gg * 4 + 0];
    float b1v = bias[g0 + gg * 4 + 1];
    float b2v = bias[g0 + gg * 4 + 2];
    float b3v = bias[g0 + gg * 4 + 3];
#pragma unroll
    for (int ti = 0; ti < 4; ti++) {
        int tok = tt * 32 + tg * 4 + ti;
        float4 o = make_float4(acc[0][ti] + b0v, acc[1][ti] + b1v,
                               acc[2][ti] + b2v, acc[3][ti] + b3v);
        *(float4*)&g_xg[dir][tok * G_ + g0 + gg * 4] = o;
    }
}

// ---------------- Kernel B: HMMA LSTM, 3-plane bf16 split (fp32-exact) ---
// 128 CTAs x 256 thr: (dir 2) x (utile 16: M=64 rows = gate*16+ul) x
// (btile 4: N=32 batches). Warp = (gate mt = w&3, k-half kh = w>>2,
// K=128 each). A planes w0/w1/w2 resident in regs (96). Per step: stage h
// 3 planes (pitch 264 bf16) -> 8 kt x (6 ldmatrix + 24 mma) -> Gex[2]
// partial-sum exchange -> fp32 epilogue -> h 3-plane bf16 to gmem.
// Products: a0b0,a0b1,a1b0,a1b1,a0b2,a2b0 (err ~2^-27 + fp32 accum).
// SMEM: Bsm 3x[32][264]bf16 @0 (50688B) | Gex [2][4][16][34]f32 @50688
// (17408B). Total 68096. Sync: distinct-line flags, 16-CTA domain.
__global__ void __launch_bounds__(256, 1)
lstm_kernel(const float* __restrict__ Whhf, const float* __restrict__ Whhb) {
    extern __shared__ char sp[];
    uint32_t sbase = smem_u32(sp);
    const int off_G = 50688;
    float* Gex = (float*)(sp + off_G);   // [kh 2][gate 4][u 16][b 34]

    int bx    = blockIdx.x;
    int dir   = bx >> 6;
    int cid   = bx & 63;
    int btile = cid & 3;
    int utile = cid >> 2;
    int b0 = btile * 32, u0 = utile * 16;
    const float* Whh = dir ? Whhb : Whhf;

    int tid = threadIdx.x, w = tid >> 5, lane = tid & 31;
    int mt = w & 3;     // gate (m-tile)
    int kh = w >> 2;    // k-half (0..1), 128 k each

    // ldmatrix lane addresses (pitch 528B = 264 bf16; 132 words ≡ 4 mod 32 -> conflict-free)
    uint32_t a_lane = sbase + (uint32_t)((mt * 16 + (lane & 15)) * 528 + (lane >> 4) * 16);
    uint32_t b_lane = sbase + (uint32_t)(((((lane >> 4) & 1) * 8 + (lane & 7)) * 528) + ((lane >> 3) & 1) * 16);
    uint32_t khoff = (uint32_t)(kh * 256);

    uint32_t af0[8][4], af1[8][4], af2[8][4];

    // ---- one-time A fragment load: three planes ----
    {
        __nv_bfloat16* Asm = (__nv_bfloat16*)sp;
#pragma unroll 1
        for (int p = 0; p < 3; p++) {
            for (int idx = tid; idx < 64 * 256; idx += 256) {
                int r = idx >> 8, k = idx & 255;
                int gate = r >> 4, ul = r & 15;
                float wv = Whh[(gate * 256 + u0 + ul) * 256 + k];
                float w0 = __bfloat162float(__float2bfloat16(wv));
                __nv_bfloat16 o;
                if (p == 0) o = __float2bfloat16(wv);
                else if (p == 1) o = __float2bfloat16(wv - w0);
                else {
                    float w1 = __bfloat162float(__float2bfloat16(wv - w0));
                    o = __float2bfloat16(wv - w0 - w1);
                }
                Asm[r * 264 + k] = o;
            }
            __syncthreads();
            if (p == 0) {
#pragma unroll
                for (int kt = 0; kt < 8; kt++) LDMX4(af0[kt], a_lane + khoff + kt * 32);
            } else if (p == 1) {
#pragma unroll
                for (int kt = 0; kt < 8; kt++) LDMX4(af1[kt], a_lane + khoff + kt * 32);
            } else {
#pragma unroll
                for (int kt = 0; kt < 8; kt++) LDMX4(af2[kt], a_lane + khoff + kt * 32);
            }
            __syncthreads();
        }
    }

    // epilogue cell assignment: thread = (unit ut, batches b2, b2+1)
    int ut = tid >> 4;
    int b2 = (tid & 15) * 2;
    float cst[2] = {0.f, 0.f};

    for (int ts = 0; ts < S_; ts++) {
        int t = dir ? (S_ - 1 - ts) : ts;

        // prefetch xg (independent of flag-gated h)
        float xv[2][4];
#pragma unroll
        for (int c = 0; c < 2; c++) {
            const float* xp = &g_xg[dir][(t * B_ + b0 + b2 + c) * G_ + u0 + ut];
#pragma unroll
            for (int g = 0; g < 4; g++) xv[c][g] = xp[g * 256];
        }

        if (ts > 0) {
            // wait for the 16 CTAs of this (dir,btile) group: step ts-1 done
            if (tid < 16) {
                volatile unsigned* fr = &g_flagx[dir][btile][tid][0];
                unsigned v;
                do { v = *fr; } while (!__all_sync(0xFFFFu, v >= (unsigned)ts));
                __threadfence();
            }
            __syncthreads();

            // stage B = h(prev) 3 planes [32 b][256 k] -> pitch 264 bf16
            int tp = dir ? (t + 1) : (t - 1);
            const __nv_bfloat16* hbase = &g_h3[dir][tp][0][b0][0];
#pragma unroll
            for (int it = 0; it < 12; it++) {
                int idx = tid + it * 256;       // 0..3071 uint4 moves
                int r = idx >> 5, q = idx & 31; // r: plane*32+batch, q: 8-bf16 chunk
                int p = r >> 5, bI = r & 31;
                uint4 v = *(const uint4*)(hbase + p * (B_ * H_) + bI * H_ + q * 8);
                *(uint4*)(sp + p * 16896 + bI * 528 + q * 16) = v;
            }
            __syncthreads();

            float dacc[4][4];
#pragma unroll
            for (int j = 0; j < 4; j++)
#pragma unroll
                for (int q = 0; q < 4; q++) dacc[j][q] = 0.f;

#pragma unroll
            for (int kt = 0; kt < 8; kt++) {
                uint32_t kb = khoff + kt * 32;
                uint32_t q0[8], q1[8], q2[8];
                LDMX4(q0,     b_lane + kb);
                LDMX4(q0 + 4, b_lane + 8448 + kb);
                LDMX4(q1,     b_lane + 16896 + kb);
                LDMX4(q1 + 4, b_lane + 16896 + 8448 + kb);
                LDMX4(q2,     b_lane + 33792 + kb);
                LDMX4(q2 + 4, b_lane + 33792 + 8448 + kb);
#pragma unroll
                for (int j = 0; j < 4; j++) {
                    const uint32_t* b0p = q0 + (j >> 1) * 4 + (j & 1) * 2;
                    const uint32_t* b1p = q1 + (j >> 1) * 4 + (j & 1) * 2;
                    const uint32_t* b2p = q2 + (j >> 1) * 4 + (j & 1) * 2;
                    mma16816(dacc[j], af0[kt], b0p);   // a0 b0
                    mma16816(dacc[j], af1[kt], b0p);   // a1 b0
                    mma16816(dacc[j], af2[kt], b0p);   // a2 b0
                    mma16816(dacc[j], af0[kt], b1p);   // a0 b1
                    mma16816(dacc[j], af1[kt], b1p);   // a1 b1
                    mma16816(dacc[j], af0[kt], b2p);   // a0 b2
                }
            }

            // Gex partial-sum exchange: [kh][gate][unit][batch]
            {
                float* gbase = &Gex[kh * 2176 + mt * 544];
                int r0 = lane >> 2;
                int c0 = (lane & 3) * 2;
#pragma unroll
                for (int j = 0; j < 4; j++) {
                    int cb = j * 8 + c0;
                    *(float2*)&gbase[r0 * 34 + cb]       = make_float2(dacc[j][0], dacc[j][1]);
                    *(float2*)&gbase[(r0 + 8) * 34 + cb] = make_float2(dacc[j][2], dacc[j][3]);
                }
            }
            __syncthreads();
        }

        // ---- epilogue: 2 cells per thread ----
#pragma unroll
        for (int c = 0; c < 2; c++) {
            float ai = xv[c][0], af = xv[c][1], ag = xv[c][2], ao = xv[c][3];
            if (ts > 0) {
                int gi = ut * 34 + b2 + c;
                ai += Gex[0 * 544 + gi] + Gex[2176 + 0 * 544 + gi];
                af += Gex[1 * 544 + gi] + Gex[2176 + 1 * 544 + gi];
                ag += Gex[2 * 544 + gi] + Gex[2176 + 2 * 544 + gi];
                ao += Gex[3 * 544 + gi] + Gex[2176 + 3 * 544 + gi];
            }
            cst[c] = fsig(af) * cst[c] + fsig(ai) * ftanh(ag);
            float h = fsig(ao) * ftanh(cst[c]);
            float h0 = __bfloat162float(__float2bfloat16(h));
            float r1 = h - h0;
            float h1 = __bfloat162float(__float2bfloat16(r1));
            __nv_bfloat16* hd = &g_h3[dir][t][0][b0 + b2 + c][u0 + ut];
            hd[0]            = __float2bfloat16(h);
            hd[B_ * H_]      = __float2bfloat16(r1);
            hd[2 * B_ * H_]  = __float2bfloat16(r1 - h1);
        }

        // release: h visible, then publish flag
        __threadfence();
        __syncthreads();
        if (tid == 0)
            *(volatile unsigned*)&g_flagx[dir][btile][utile][0] = (unsigned)(ts + 1);
    }
}

// ---------------- Kernel C: MLP emissions (3-plane bf16 h) ---------------
__global__ void mlp_kernel(const float* __restrict__ mlpW,
                           const float* __restrict__ mlpb) {
    __shared__ float Wsm[T_ * 2 * H_];
    for (int i = threadIdx.x; i < T_ * 2 * H_; i += 128) Wsm[i] = mlpW[i];
    __syncthreads();

    int s = blockIdx.x;
    int b = threadIdx.x;

    float acc[T_];
#pragma unroll
    for (int t = 0; t < T_; t++) acc[t] = 0.f;

    const int PS = B_ * H_ / 2;  // plane stride in bfloat162
    const __nv_bfloat162* hf = (const __nv_bfloat162*)&g_h3[0][s][0][b][0];
    const __nv_bfloat162* hb = (const __nv_bfloat162*)&g_h3[1][s][0][b][0];
#pragma unroll 4
    for (int k2 = 0; k2 < 128; k2++) {
        __nv_bfloat162 f0 = hf[k2], f1 = hf[PS + k2], f2 = hf[2 * PS + k2];
        __nv_bfloat162 g0 = hb[k2], g1 = hb[PS + k2], g2 = hb[2 * PS + k2];
        float fa = __bfloat162float(f0.x) + __bfloat162float(f1.x) + __bfloat162float(f2.x);
        float fb = __bfloat162float(f0.y) + __bfloat162float(f1.y) + __bfloat162float(f2.y);
        float ga = __bfloat162float(g0.x) + __bfloat162float(g1.x) + __bfloat162float(g2.x);
        float gb = __bfloat162float(g0.y) + __bfloat162float(g1.y) + __bfloat162float(g2.y);
        int k = k2 * 2;
#pragma unroll
        for (int t = 0; t < T_; t++) {
            acc[t] += fa * Wsm[t * 512 + k]       + fb * Wsm[t * 512 + k + 1];
            acc[t] += ga * Wsm[t * 512 + 256 + k] + gb * Wsm[t * 512 + 257 + k];
        }
    }
#pragma unroll
    for (int t = 0; t < T_; t++)
        g_em[(b * S_ + s) * T_ + t] = acc[t] + mlpb[t];
}

// ---------------- Kernel D: CRF Viterbi (one warp per batch) -------------
__global__ void viterbi_kernel(const int* __restrict__ data,
                               const float* __restrict__ stt,
                               const float* __restrict__ trn,
                               const float* __restrict__ ett,
                               float* __restrict__ out) {
    __shared__ int sbp[2][S_][10];
    int w = threadIdx.x >> 5, lane = threadIdx.x & 31;
    int b = blockIdx.x * 2 + w;
    int cc = lane < T_ ? lane : (T_ - 1);

    int cnt = 0;
    for (int s = lane; s < S_; s += 32) cnt += (data[b * S_ + s] != 0);
    for (int off = 16; off; off >>= 1) cnt += __shfl_xor_sync(0xFFFFFFFFu, cnt, off);
    int len = cnt;

    float tr[T_];
#pragma unroll
    for (int p = 0; p < T_; p++) tr[p] = trn[p * T_ + cc];

    float score = stt[cc] + g_em[(b * S_ + 0) * T_ + cc];
    float e_next = g_em[(b * S_ + 1) * T_ + cc];

    for (int t = 1; t < S_; t++) {
        float e = e_next;
        if (t + 1 < S_) e_next = g_em[(b * S_ + t + 1) * T_ + cc];
        float best = -1e30f; int bp = 0;
#pragma unroll
        for (int p = 0; p < T_; p++) {
            float sp = __shfl_sync(0xFFFFFFFFu, score, p);
            float cand = sp + tr[p] + e;
            if (cand > best) { best = cand; bp = p; }   // first-max tie-break
        }
        if (lane < T_) sbp[w][t][lane] = bp;
        if (t < len) score = best;
    }

    float fin = score + ett[cc];
    float bestf = -1e30f; int tag = 0;
#pragma unroll
    for (int p = 0; p < T_; p++) {
        float v = __shfl_sync(0xFFFFFFFFu, fin, p);
        if (v > bestf) { bestf = v; tag = p; }
    }
    if (lane == 0) out[B_ * S_ + b] = bestf;

    if (lane == 0) out[b * S_ + (S_ - 1)] = ((S_ - 1) < len) ? (float)tag : 0.f;
    for (int s2 = S_ - 2; s2 >= 0; s2--) {
        int bpv = sbp[w][s2 + 1][cc];
        int prev = __shfl_sync(0xFFFFFFFFu, bpv, tag);
        if (s2 + 1 < len) tag = prev;
        if (lane == 0) out[b * S_ + s2] = (s2 < len) ? (float)tag : 0.f;
    }
}

// ---------------- launch ----------------
extern "C" void kernel_launch(void* const* d_in, const int* in_sizes, int n_in,
                              void* d_out, int out_size) {
    const int*   data = (const int*)d_in[0];
    // d_in[1] = mask (ignored; mask == (data != 0))
    const float* emb  = (const float*)d_in[2];
    const float* Wihf = (const float*)d_in[3];
    const float* Whhf = (const float*)d_in[4];
    const float* bf   = (const float*)d_in[5];
    const float* Wihb = (const float*)d_in[6];
    const float* Whhb = (const float*)d_in[7];
    const float* bb   = (const float*)d_in[8];
    const float* mlpW = (const float*)d_in[9];
    const float* mlpb = (const float*)d_in[10];
    const float* stt  = (const float*)d_in[11];
    const float* trn  = (const float*)d_in[12];
    const float* ett  = (const float*)d_in[13];
    float* out = (float*)d_out;

    cudaFuncSetAttribute(xg_kernel,   cudaFuncAttributeMaxDynamicSharedMemorySize, 67200);
    cudaFuncSetAttribute(lstm_kernel, cudaFuncAttributeMaxDynamicSharedMemorySize, 68096);

    reset_kernel<<<8, 512>>>();
    dim3 gA(2048, 16);
    xg_kernel<<<gA, 256, 67200>>>(data, emb, Wihf, bf, Wihb, bb);
    lstm_kernel<<<128, 256, 68096>>>(Whhf, Whhb);
    mlp_kernel<<<512, 128>>>(mlpW, mlpb);
    viterbi_kernel<<<64, 64>>>(data, stt, trn, ett, out);
}

// round 13
// speedup vs baseline: 3.3982x; 1.3811x over previous
#include <cuda_runtime.h>
#include <cuda_bf16.h>
#include <cstdint>

// Problem dims
#define S_ 512
#define B_ 128
#define E_ 100
#define H_ 256
#define T_ 9
#define G_ 1024   // 4*H
#define V_ 6000
#define VPAD 6016

// ---------------- scratch (device globals; no allocations) ----------------
__device__ float g_tab[2][VPAD * G_];            // vocab projection table (+bias)
__device__ __nv_bfloat16 g_h3[2][S_][3][B_][H_]; // h 3-plane bf16 split (MMA B operand)
__device__ float g_hT[2][S_ * H_ * B_];          // fp32 h transposed [s][u][b] (for MLP)
__device__ float g_em[B_ * S_ * T_];             // emissions [b][s][t]
__device__ unsigned g_flagx[2][4][16][32];       // flags [dir][btile][utile], own 128B line

__device__ __forceinline__ float fsig(float x) {
    return __fdividef(1.f, 1.f + __expf(-x));
}
__device__ __forceinline__ float ftanh(float x) {
    return __fdividef(2.f, 1.f + __expf(-2.f * x)) - 1.f;
}

__device__ __forceinline__ uint32_t smem_u32(const void* p) {
    uint32_t a;
    asm("{ .reg .u64 t; cvta.to.shared.u64 t, %1; cvt.u32.u64 %0, t; }"
        : "=r"(a) : "l"(p));
    return a;
}

#define LDMX4(r, addr) \
    asm volatile("ldmatrix.sync.aligned.m8n8.x4.shared.b16 {%0,%1,%2,%3}, [%4];" \
        : "=r"((r)[0]), "=r"((r)[1]), "=r"((r)[2]), "=r"((r)[3]) : "r"(addr))

__device__ __forceinline__ void mma16816(float* d, const uint32_t* a, const uint32_t* b) {
    asm volatile(
        "mma.sync.aligned.m16n8k16.row.col.f32.bf16.bf16.f32 "
        "{%0,%1,%2,%3}, {%4,%5,%6,%7}, {%8,%9}, {%0,%1,%2,%3};"
        : "+f"(d[0]), "+f"(d[1]), "+f"(d[2]), "+f"(d[3])
        : "r"(a[0]), "r"(a[1]), "r"(a[2]), "r"(a[3]), "r"(b[0]), "r"(b[1]));
}

__global__ void reset_kernel() {
    int i = blockIdx.x * blockDim.x + threadIdx.x;
    if (i < 2 * 4 * 16 * 32) ((unsigned*)g_flagx)[i] = 0u;
}

// ---------------- Kernel A: VOCAB projection (not per-token!) -------------
// tab[dir][v][g] = sum_k emb[v][k] * W_ih[g][k] + bias[g], for v < 6000.
// 2.46 G MAC total vs 13.4 G for per-token. grid = (188 vocab tiles, 16).
__global__ void vocab_kernel(const float* __restrict__ emb,
                             const float* __restrict__ Wf,
                             const float* __restrict__ bf,
                             const float* __restrict__ Wb,
                             const float* __restrict__ bb) {
    extern __shared__ float sm[];
    float* Xsm = sm;          // [100][36]
    float* Wsm = sm + 3600;   // [100][132]

    int tt  = blockIdx.x;
    int gt  = blockIdx.y;
    int dir = gt >> 3;
    int g0  = (gt & 7) * 128;
    const float* W    = dir ? Wb : Wf;
    const float* bias = dir ? bb : bf;

    for (int idx = threadIdx.x; idx < 32 * E_; idx += 256) {
        int j = idx / E_, k = idx - j * E_;
        int v = tt * 32 + j;
        int row = (v < V_) ? v : 0;
        Xsm[k * 36 + j] = emb[row * E_ + k];
    }
    for (int idx = threadIdx.x; idx < 128 * E_; idx += 256) {
        int r = idx / E_, k = idx - r * E_;
        Wsm[k * 132 + r] = W[(g0 + r) * E_ + k];
    }
    __syncthreads();

    int gg = threadIdx.x & 31;
    int tg = threadIdx.x >> 5;
    float acc[4][4];
#pragma unroll
    for (int i = 0; i < 4; i++)
#pragma unroll
        for (int j = 0; j < 4; j++) acc[i][j] = 0.f;

    const float* wp = &Wsm[gg * 4];
    const float* xp = &Xsm[tg * 4];
    for (int k = 0; k < E_; k++) {
        float4 w = *(const float4*)(wp + k * 132);
        float4 x = *(const float4*)(xp + k * 36);
        acc[0][0] += w.x * x.x; acc[0][1] += w.x * x.y; acc[0][2] += w.x * x.z; acc[0][3] += w.x * x.w;
        acc[1][0] += w.y * x.x; acc[1][1] += w.y * x.y; acc[1][2] += w.y * x.z; acc[1][3] += w.y * x.w;
        acc[2][0] += w.z * x.x; acc[2][1] += w.z * x.y; acc[2][2] += w.z * x.z; acc[2][3] += w.z * x.w;
        acc[3][0] += w.w * x.x; acc[3][1] += w.w * x.y; acc[3][2] += w.w * x.z; acc[3][3] += w.w * x.w;
    }

    float b0v = bias[g0 + gg * 4 + 0];
    float b1v = bias[g0 + gg * 4 + 1];
    float b2v = bias[g0 + gg * 4 + 2];
    float b3v = bias[g0 + gg * 4 + 3];
#pragma unroll
    for (int ti = 0; ti < 4; ti++) {
        int v = tt * 32 + tg * 4 + ti;
        if (v < V_) {
            float4 o = make_float4(acc[0][ti] + b0v, acc[1][ti] + b1v,
                                   acc[2][ti] + b2v, acc[3][ti] + b3v);
            *(float4*)&g_tab[dir][v * G_ + g0 + gg * 4] = o;
        }
    }
}

// ---------------- Kernel B: HMMA LSTM, 3-plane bf16 split (fp32-exact) ---
// Same machinery as R12 (PASSED, rel_err 1.7e-7). Changes: xg gathered
// directly from the vocab table via data[b][t] (no g_xg stream), and the
// epilogue additionally stores fp32 h transposed for the MLP.
__global__ void __launch_bounds__(256, 1)
lstm_kernel(const float* __restrict__ Whhf, const float* __restrict__ Whhb,
            const int* __restrict__ data) {
    extern __shared__ char sp[];
    uint32_t sbase = smem_u32(sp);
    const int off_G = 50688;
    float* Gex = (float*)(sp + off_G);   // [kh 2][gate 4][u 16][b 34]

    int bx    = blockIdx.x;
    int dir   = bx >> 6;
    int cid   = bx & 63;
    int btile = cid & 3;
    int utile = cid >> 2;
    int b0 = btile * 32, u0 = utile * 16;
    const float* Whh = dir ? Whhb : Whhf;

    int tid = threadIdx.x, w = tid >> 5, lane = tid & 31;
    int mt = w & 3;     // gate (m-tile)
    int kh = w >> 2;    // k-half (0..1), 128 k each

    // ldmatrix lane addresses (pitch 528B = 264 bf16)
    uint32_t a_lane = sbase + (uint32_t)((mt * 16 + (lane & 15)) * 528 + (lane >> 4) * 16);
    uint32_t b_lane = sbase + (uint32_t)(((((lane >> 4) & 1) * 8 + (lane & 7)) * 528) + ((lane >> 3) & 1) * 16);
    uint32_t khoff = (uint32_t)(kh * 256);

    uint32_t af0[8][4], af1[8][4], af2[8][4];

    // ---- one-time A fragment load: three planes ----
    {
        __nv_bfloat16* Asm = (__nv_bfloat16*)sp;
#pragma unroll 1
        for (int p = 0; p < 3; p++) {
            for (int idx = tid; idx < 64 * 256; idx += 256) {
                int r = idx >> 8, k = idx & 255;
                int gate = r >> 4, ul = r & 15;
                float wv = Whh[(gate * 256 + u0 + ul) * 256 + k];
                float w0 = __bfloat162float(__float2bfloat16(wv));
                __nv_bfloat16 o;
                if (p == 0) o = __float2bfloat16(wv);
                else if (p == 1) o = __float2bfloat16(wv - w0);
                else {
                    float w1 = __bfloat162float(__float2bfloat16(wv - w0));
                    o = __float2bfloat16(wv - w0 - w1);
                }
                Asm[r * 264 + k] = o;
            }
            __syncthreads();
            if (p == 0) {
#pragma unroll
                for (int kt = 0; kt < 8; kt++) LDMX4(af0[kt], a_lane + khoff + kt * 32);
            } else if (p == 1) {
#pragma unroll
                for (int kt = 0; kt < 8; kt++) LDMX4(af1[kt], a_lane + khoff + kt * 32);
            } else {
#pragma unroll
                for (int kt = 0; kt < 8; kt++) LDMX4(af2[kt], a_lane + khoff + kt * 32);
            }
            __syncthreads();
        }
    }

    // epilogue cell assignment: thread = (unit ut, batches b2, b2+1)
    int ut = tid >> 4;
    int b2 = (tid & 15) * 2;
    float cst[2] = {0.f, 0.f};
    const float* tab = g_tab[dir];

    for (int ts = 0; ts < S_; ts++) {
        int t = dir ? (S_ - 1 - ts) : ts;

        // prefetch xg from the vocab table (independent of flag-gated h)
        int tokA = data[(b0 + b2) * S_ + t];
        int tokB = data[(b0 + b2 + 1) * S_ + t];
        float xv[2][4];
        {
            const float* xa = &tab[tokA * G_ + u0 + ut];
            const float* xb = &tab[tokB * G_ + u0 + ut];
#pragma unroll
            for (int g = 0; g < 4; g++) { xv[0][g] = xa[g * 256]; xv[1][g] = xb[g * 256]; }
        }

        if (ts > 0) {
            // wait for the 16 CTAs of this (dir,btile) group: step ts-1 done
            if (tid < 16) {
                volatile unsigned* fr = &g_flagx[dir][btile][tid][0];
                unsigned v;
                do { v = *fr; } while (!__all_sync(0xFFFFu, v >= (unsigned)ts));
                __threadfence();
            }
            __syncthreads();

            // stage B = h(prev) 3 planes [32 b][256 k] -> pitch 264 bf16
            int tp = dir ? (t + 1) : (t - 1);
            const __nv_bfloat16* hbase = &g_h3[dir][tp][0][b0][0];
#pragma unroll
            for (int it = 0; it < 12; it++) {
                int idx = tid + it * 256;       // 0..3071 uint4 moves
                int r = idx >> 5, q = idx & 31;
                int p = r >> 5, bI = r & 31;
                uint4 v = *(const uint4*)(hbase + p * (B_ * H_) + bI * H_ + q * 8);
                *(uint4*)(sp + p * 16896 + bI * 528 + q * 16) = v;
            }
            __syncthreads();

            float dacc[4][4];
#pragma unroll
            for (int j = 0; j < 4; j++)
#pragma unroll
                for (int q = 0; q < 4; q++) dacc[j][q] = 0.f;

#pragma unroll
            for (int kt = 0; kt < 8; kt++) {
                uint32_t kb = khoff + kt * 32;
                uint32_t q0[8], q1[8], q2[8];
                LDMX4(q0,     b_lane + kb);
                LDMX4(q0 + 4, b_lane + 8448 + kb);
                LDMX4(q1,     b_lane + 16896 + kb);
                LDMX4(q1 + 4, b_lane + 16896 + 8448 + kb);
                LDMX4(q2,     b_lane + 33792 + kb);
                LDMX4(q2 + 4, b_lane + 33792 + 8448 + kb);
#pragma unroll
                for (int j = 0; j < 4; j++) {
                    const uint32_t* b0p = q0 + (j >> 1) * 4 + (j & 1) * 2;
                    const uint32_t* b1p = q1 + (j >> 1) * 4 + (j & 1) * 2;
                    const uint32_t* b2p = q2 + (j >> 1) * 4 + (j & 1) * 2;
                    mma16816(dacc[j], af0[kt], b0p);   // a0 b0
                    mma16816(dacc[j], af1[kt], b0p);   // a1 b0
                    mma16816(dacc[j], af2[kt], b0p);   // a2 b0
                    mma16816(dacc[j], af0[kt], b1p);   // a0 b1
                    mma16816(dacc[j], af1[kt], b1p);   // a1 b1
                    mma16816(dacc[j], af0[kt], b2p);   // a0 b2
                }
            }

            // Gex partial-sum exchange: [kh][gate][unit][batch]
            {
                float* gbase = &Gex[kh * 2176 + mt * 544];
                int r0 = lane >> 2;
                int c0 = (lane & 3) * 2;
#pragma unroll
                for (int j = 0; j < 4; j++) {
                    int cb = j * 8 + c0;
                    *(float2*)&gbase[r0 * 34 + cb]       = make_float2(dacc[j][0], dacc[j][1]);
                    *(float2*)&gbase[(r0 + 8) * 34 + cb] = make_float2(dacc[j][2], dacc[j][3]);
                }
            }
            __syncthreads();
        }

        // ---- epilogue: 2 cells per thread ----
#pragma unroll
        for (int c = 0; c < 2; c++) {
            float ai = xv[c][0], af = xv[c][1], ag = xv[c][2], ao = xv[c][3];
            if (ts > 0) {
                int gi = ut * 34 + b2 + c;
                ai += Gex[0 * 544 + gi] + Gex[2176 + 0 * 544 + gi];
                af += Gex[1 * 544 + gi] + Gex[2176 + 1 * 544 + gi];
                ag += Gex[2 * 544 + gi] + Gex[2176 + 2 * 544 + gi];
                ao += Gex[3 * 544 + gi] + Gex[2176 + 3 * 544 + gi];
            }
            cst[c] = fsig(af) * cst[c] + fsig(ai) * ftanh(ag);
            float h = fsig(ao) * ftanh(cst[c]);
            float h0 = __bfloat162float(__float2bfloat16(h));
            float r1 = h - h0;
            float h1 = __bfloat162float(__float2bfloat16(r1));
            __nv_bfloat16* hd = &g_h3[dir][t][0][b0 + b2 + c][u0 + ut];
            hd[0]            = __float2bfloat16(h);
            hd[B_ * H_]      = __float2bfloat16(r1);
            hd[2 * B_ * H_]  = __float2bfloat16(r1 - h1);
            // fp32 transposed copy for MLP
            g_hT[dir][(t * H_ + u0 + ut) * B_ + b0 + b2 + c] = h;
        }

        // release: h visible, then publish flag
        __threadfence();
        __syncthreads();
        if (tid == 0)
            *(volatile unsigned*)&g_flagx[dir][btile][utile][0] = (unsigned)(ts + 1);
    }
}

// ---------------- Kernel C: MLP emissions (fp32 transposed h) ------------
__global__ void mlp_kernel(const float* __restrict__ mlpW,
                           const float* __restrict__ mlpb) {
    __shared__ float Wsm[T_ * 2 * H_];
    for (int i = threadIdx.x; i < T_ * 2 * H_; i += 128) Wsm[i] = mlpW[i];
    __syncthreads();

    int s = blockIdx.x;
    int b = threadIdx.x;

    float acc[T_];
#pragma unroll
    for (int t = 0; t < T_; t++) acc[t] = 0.f;

    const float* hf = &g_hT[0][(s * H_) * B_ + b];
    const float* hb = &g_hT[1][(s * H_) * B_ + b];
#pragma unroll 4
    for (int k = 0; k < H_; k++) {
        float v1 = hf[k * B_];
        float v2 = hb[k * B_];
#pragma unroll
        for (int t = 0; t < T_; t++) {
            acc[t] += v1 * Wsm[t * 512 + k];
            acc[t] += v2 * Wsm[t * 512 + 256 + k];
        }
    }
#pragma unroll
    for (int t = 0; t < T_; t++)
        g_em[(b * S_ + s) * T_ + t] = acc[t] + mlpb[t];
}

// ---------------- Kernel D: CRF Viterbi (one warp per batch) -------------
__global__ void viterbi_kernel(const int* __restrict__ data,
                               const float* __restrict__ stt,
                               const float* __restrict__ trn,
                               const float* __restrict__ ett,
                               float* __restrict__ out) {
    __shared__ int sbp[2][S_][10];
    int w = threadIdx.x >> 5, lane = threadIdx.x & 31;
    int b = blockIdx.x * 2 + w;
    int cc = lane < T_ ? lane : (T_ - 1);

    int cnt = 0;
    for (int s = lane; s < S_; s += 32) cnt += (data[b * S_ + s] != 0);
    for (int off = 16; off; off >>= 1) cnt += __shfl_xor_sync(0xFFFFFFFFu, cnt, off);
    int len = cnt;

    float tr[T_];
#pragma unroll
    for (int p = 0; p < T_; p++) tr[p] = trn[p * T_ + cc];

    float score = stt[cc] + g_em[(b * S_ + 0) * T_ + cc];
    float e_next = g_em[(b * S_ + 1) * T_ + cc];

    for (int t = 1; t < S_; t++) {
        float e = e_next;
        if (t + 1 < S_) e_next = g_em[(b * S_ + t + 1) * T_ + cc];
        float best = -1e30f; int bp = 0;
#pragma unroll
        for (int p = 0; p < T_; p++) {
            float sp = __shfl_sync(0xFFFFFFFFu, score, p);
            float cand = sp + tr[p] + e;
            if (cand > best) { best = cand; bp = p; }   // first-max tie-break
        }
        if (lane < T_) sbp[w][t][lane] = bp;
        if (t < len) score = best;
    }

    float fin = score + ett[cc];
    float bestf = -1e30f; int tag = 0;
#pragma unroll
    for (int p = 0; p < T_; p++) {
        float v = __shfl_sync(0xFFFFFFFFu, fin, p);
        if (v > bestf) { bestf = v; tag = p; }
    }
    if (lane == 0) out[B_ * S_ + b] = bestf;

    if (lane == 0) out[b * S_ + (S_ - 1)] = ((S_ - 1) < len) ? (float)tag : 0.f;
    for (int s2 = S_ - 2; s2 >= 0; s2--) {
        int bpv = sbp[w][s2 + 1][cc];
        int prev = __shfl_sync(0xFFFFFFFFu, bpv, tag);
        if (s2 + 1 < len) tag = prev;
        if (lane == 0) out[b * S_ + s2] = (s2 < len) ? (float)tag : 0.f;
    }
}

// ---------------- launch ----------------
extern "C" void kernel_launch(void* const* d_in, const int* in_sizes, int n_in,
                              void* d_out, int out_size) {
    const int*   data = (const int*)d_in[0];
    // d_in[1] = mask (ignored; mask == (data != 0))
    const float* emb  = (const float*)d_in[2];
    const float* Wihf = (const float*)d_in[3];
    const float* Whhf = (const float*)d_in[4];
    const float* bf   = (const float*)d_in[5];
    const float* Wihb = (const float*)d_in[6];
    const float* Whhb = (const float*)d_in[7];
    const float* bb   = (const float*)d_in[8];
    const float* mlpW = (const float*)d_in[9];
    const float* mlpb = (const float*)d_in[10];
    const float* stt  = (const float*)d_in[11];
    const float* trn  = (const float*)d_in[12];
    const float* ett  = (const float*)d_in[13];
    float* out = (float*)d_out;

    cudaFuncSetAttribute(vocab_kernel, cudaFuncAttributeMaxDynamicSharedMemorySize, 67200);
    cudaFuncSetAttribute(lstm_kernel,  cudaFuncAttributeMaxDynamicSharedMemorySize, 68096);

    reset_kernel<<<8, 512>>>();
    dim3 gV(188, 16);
    vocab_kernel<<<gV, 256, 67200>>>(emb, Wihf, bf, Wihb, bb);
    lstm_kernel<<<128, 256, 68096>>>(Whhf, Whhb, data);
    mlp_kernel<<<512, 128>>>(mlpW, mlpb);
    viterbi_kernel<<<64, 64>>>(data, stt, trn, ett, out);
}

// round 14
// speedup vs baseline: 4.1916x; 1.2335x over previous
#include <cuda_runtime.h>
#include <cuda_bf16.h>
#include <cuda_fp16.h>
#include <cstdint>

// Problem dims
#define S_ 512
#define B_ 128
#define E_ 100
#define H_ 256
#define T_ 9
#define G_ 1024   // 4*H
#define V_ 6000
#define VPAD 6016

// ---------------- scratch (device globals; no allocations) ----------------
__device__ float g_tab[2][VPAD * G_];            // vocab projection table (+bias)
__device__ __half g_h2[2][S_][2][B_][H_];        // h 2-plane fp16 split (MMA B operand)
__device__ float g_hT[2][S_ * H_ * B_];          // fp32 h transposed [s][u][b] (for MLP)
__device__ float g_em[B_ * S_ * T_];             // emissions [b][s][t]
__device__ unsigned g_flagx[2][4][16][32];       // flags [dir][btile][utile], own 128B line

__device__ __forceinline__ float fsig(float x) {
    return __fdividef(1.f, 1.f + __expf(-x));
}
__device__ __forceinline__ float ftanh(float x) {
    return __fdividef(2.f, 1.f + __expf(-2.f * x)) - 1.f;
}

__device__ __forceinline__ uint32_t smem_u32(const void* p) {
    uint32_t a;
    asm("{ .reg .u64 t; cvta.to.shared.u64 t, %1; cvt.u32.u64 %0, t; }"
        : "=r"(a) : "l"(p));
    return a;
}

#define LDMX4(r, addr) \
    asm volatile("ldmatrix.sync.aligned.m8n8.x4.shared.b16 {%0,%1,%2,%3}, [%4];" \
        : "=r"((r)[0]), "=r"((r)[1]), "=r"((r)[2]), "=r"((r)[3]) : "r"(addr))

__device__ __forceinline__ void mma16816h(float* d, const uint32_t* a, const uint32_t* b) {
    asm volatile(
        "mma.sync.aligned.m16n8k16.row.col.f32.f16.f16.f32 "
        "{%0,%1,%2,%3}, {%4,%5,%6,%7}, {%8,%9}, {%0,%1,%2,%3};"
        : "+f"(d[0]), "+f"(d[1]), "+f"(d[2]), "+f"(d[3])
        : "r"(a[0]), "r"(a[1]), "r"(a[2]), "r"(a[3]), "r"(b[0]), "r"(b[1]));
}

__global__ void reset_kernel() {
    int i = blockIdx.x * blockDim.x + threadIdx.x;
    if (i < 2 * 4 * 16 * 32) ((unsigned*)g_flagx)[i] = 0u;
}

// ---------------- Kernel A: VOCAB projection (not per-token) -------------
__global__ void vocab_kernel(const float* __restrict__ emb,
                             const float* __restrict__ Wf,
                             const float* __restrict__ bf,
                             const float* __restrict__ Wb,
                             const float* __restrict__ bb) {
    extern __shared__ float sm[];
    float* Xsm = sm;          // [100][36]
    float* Wsm = sm + 3600;   // [100][132]

    int tt  = blockIdx.x;
    int gt  = blockIdx.y;
    int dir = gt >> 3;
    int g0  = (gt & 7) * 128;
    const float* W    = dir ? Wb : Wf;
    const float* bias = dir ? bb : bf;

    for (int idx = threadIdx.x; idx < 32 * E_; idx += 256) {
        int j = idx / E_, k = idx - j * E_;
        int v = tt * 32 + j;
        int row = (v < V_) ? v : 0;
        Xsm[k * 36 + j] = emb[row * E_ + k];
    }
    for (int idx = threadIdx.x; idx < 128 * E_; idx += 256) {
        int r = idx / E_, k = idx - r * E_;
        Wsm[k * 132 + r] = W[(g0 + r) * E_ + k];
    }
    __syncthreads();

    int gg = threadIdx.x & 31;
    int tg = threadIdx.x >> 5;
    float acc[4][4];
#pragma unroll
    for (int i = 0; i < 4; i++)
#pragma unroll
        for (int j = 0; j < 4; j++) acc[i][j] = 0.f;

    const float* wp = &Wsm[gg * 4];
    const float* xp = &Xsm[tg * 4];
    for (int k = 0; k < E_; k++) {
        float4 w = *(const float4*)(wp + k * 132);
        float4 x = *(const float4*)(xp + k * 36);
        acc[0][0] += w.x * x.x; acc[0][1] += w.x * x.y; acc[0][2] += w.x * x.z; acc[0][3] += w.x * x.w;
        acc[1][0] += w.y * x.x; acc[1][1] += w.y * x.y; acc[1][2] += w.y * x.z; acc[1][3] += w.y * x.w;
        acc[2][0] += w.z * x.x; acc[2][1] += w.z * x.y; acc[2][2] += w.z * x.z; acc[2][3] += w.z * x.w;
        acc[3][0] += w.w * x.x; acc[3][1] += w.w * x.y; acc[3][2] += w.w * x.z; acc[3][3] += w.w * x.w;
    }

    float b0v = bias[g0 + gg * 4 + 0];
    float b1v = bias[g0 + gg * 4 + 1];
    float b2v = bias[g0 + gg * 4 + 2];
    float b3v = bias[g0 + gg * 4 + 3];
#pragma unroll
    for (int ti = 0; ti < 4; ti++) {
        int v = tt * 32 + tg * 4 + ti;
        if (v < V_) {
            float4 o = make_float4(acc[0][ti] + b0v, acc[1][ti] + b1v,
                                   acc[2][ti] + b2v, acc[3][ti] + b3v);
            *(float4*)&g_tab[dir][v * G_ + g0 + gg * 4] = o;
        }
    }
}

// ---------------- Kernel B: HMMA LSTM, 2-plane fp16 split (3 products) ---
// Same machinery as R13 (PASSED). Split basis bf16->fp16: 11-bit planes,
// dropped product w1*h1 ~2^-22 (fp32-class error). 96 mma/warp/step.
// SMEM: Bsm 2x[32][264]fp16 @0 (33792B) | Gex [2][4][16][34]f32 @33792
// (17408B). Total 51200. Init A-phase uses [64][264]fp16 = 33792B.
__global__ void __launch_bounds__(256, 1)
lstm_kernel(const float* __restrict__ Whhf, const float* __restrict__ Whhb,
            const int* __restrict__ data) {
    extern __shared__ char sp[];
    uint32_t sbase = smem_u32(sp);
    const int off_G = 33792;
    float* Gex = (float*)(sp + off_G);   // [kh 2][gate 4][u 16][b 34]

    int bx    = blockIdx.x;
    int dir   = bx >> 6;
    int cid   = bx & 63;
    int btile = cid & 3;
    int utile = cid >> 2;
    int b0 = btile * 32, u0 = utile * 16;
    const float* Whh = dir ? Whhb : Whhf;

    int tid = threadIdx.x, w = tid >> 5, lane = tid & 31;
    int mt = w & 3;     // gate (m-tile)
    int kh = w >> 2;    // k-half (0..1), 128 k each

    // ldmatrix lane addresses (pitch 528B = 264 halfs)
    uint32_t a_lane = sbase + (uint32_t)((mt * 16 + (lane & 15)) * 528 + (lane >> 4) * 16);
    uint32_t b_lane = sbase + (uint32_t)(((((lane >> 4) & 1) * 8 + (lane & 7)) * 528) + ((lane >> 3) & 1) * 16);
    uint32_t khoff = (uint32_t)(kh * 256);

    uint32_t af0[8][4], af1[8][4];

    // ---- one-time A fragment load: two fp16 planes ----
    {
        __half* Asm = (__half*)sp;
#pragma unroll 1
        for (int p = 0; p < 2; p++) {
            for (int idx = tid; idx < 64 * 256; idx += 256) {
                int r = idx >> 8, k = idx & 255;
                int gate = r >> 4, ul = r & 15;
                float wv = Whh[(gate * 256 + u0 + ul) * 256 + k];
                __half o;
                if (p == 0) o = __float2half(wv);
                else {
                    float w0 = __half2float(__float2half(wv));
                    o = __float2half(wv - w0);
                }
                Asm[r * 264 + k] = o;
            }
            __syncthreads();
            if (p == 0) {
#pragma unroll
                for (int kt = 0; kt < 8; kt++) LDMX4(af0[kt], a_lane + khoff + kt * 32);
            } else {
#pragma unroll
                for (int kt = 0; kt < 8; kt++) LDMX4(af1[kt], a_lane + khoff + kt * 32);
            }
            __syncthreads();
        }
    }

    // epilogue cell assignment: thread = (unit ut, batches b2, b2+1)
    int ut = tid >> 4;
    int b2 = (tid & 15) * 2;
    float cst[2] = {0.f, 0.f};
    const float* tab = g_tab[dir];

    for (int ts = 0; ts < S_; ts++) {
        int t = dir ? (S_ - 1 - ts) : ts;

        // prefetch xg from the vocab table (independent of flag-gated h)
        int tokA = data[(b0 + b2) * S_ + t];
        int tokB = data[(b0 + b2 + 1) * S_ + t];
        float xv[2][4];
        {
            const float* xa = &tab[tokA * G_ + u0 + ut];
            const float* xb = &tab[tokB * G_ + u0 + ut];
#pragma unroll
            for (int g = 0; g < 4; g++) { xv[0][g] = xa[g * 256]; xv[1][g] = xb[g * 256]; }
        }

        if (ts > 0) {
            // wait for the 16 CTAs of this (dir,btile) group: step ts-1 done
            if (tid < 16) {
                volatile unsigned* fr = &g_flagx[dir][btile][tid][0];
                unsigned v;
                do { v = *fr; } while (!__all_sync(0xFFFFu, v >= (unsigned)ts));
                __threadfence();
            }
            __syncthreads();

            // stage B = h(prev) 2 planes [32 b][256 k] -> pitch 264 fp16
            int tp = dir ? (t + 1) : (t - 1);
            const __half* hbase = &g_h2[dir][tp][0][b0][0];
#pragma unroll
            for (int it = 0; it < 8; it++) {
                int idx = tid + it * 256;       // 0..2047 uint4 moves
                int r = idx >> 5, q = idx & 31; // r: plane*32+batch, q: 8-half chunk
                int p = r >> 5, bI = r & 31;
                uint4 v = *(const uint4*)(hbase + p * (B_ * H_) + bI * H_ + q * 8);
                *(uint4*)(sp + p * 16896 + bI * 528 + q * 16) = v;
            }
            __syncthreads();

            float dacc[4][4];
#pragma unroll
            for (int j = 0; j < 4; j++)
#pragma unroll
                for (int q = 0; q < 4; q++) dacc[j][q] = 0.f;

#pragma unroll
            for (int kt = 0; kt < 8; kt++) {
                uint32_t kb = khoff + kt * 32;
                uint32_t q0[8], q1[8];
                LDMX4(q0,     b_lane + kb);
                LDMX4(q0 + 4, b_lane + 8448 + kb);
                LDMX4(q1,     b_lane + 16896 + kb);
                LDMX4(q1 + 4, b_lane + 16896 + 8448 + kb);
#pragma unroll
                for (int j = 0; j < 4; j++) {
                    const uint32_t* b0p = q0 + (j >> 1) * 4 + (j & 1) * 2;
                    const uint32_t* b1p = q1 + (j >> 1) * 4 + (j & 1) * 2;
                    mma16816h(dacc[j], af0[kt], b0p);   // a0 b0
                    mma16816h(dacc[j], af1[kt], b0p);   // a1 b0
                    mma16816h(dacc[j], af0[kt], b1p);   // a0 b1
                }
            }

            // Gex partial-sum exchange: [kh][gate][unit][batch]
            {
                float* gbase = &Gex[kh * 2176 + mt * 544];
                int r0 = lane >> 2;
                int c0 = (lane & 3) * 2;
#pragma unroll
                for (int j = 0; j < 4; j++) {
                    int cb = j * 8 + c0;
                    *(float2*)&gbase[r0 * 34 + cb]       = make_float2(dacc[j][0], dacc[j][1]);
                    *(float2*)&gbase[(r0 + 8) * 34 + cb] = make_float2(dacc[j][2], dacc[j][3]);
                }
            }
            __syncthreads();
        }

        // ---- epilogue: 2 cells per thread ----
#pragma unroll
        for (int c = 0; c < 2; c++) {
            float ai = xv[c][0], af = xv[c][1], ag = xv[c][2], ao = xv[c][3];
            if (ts > 0) {
                int gi = ut * 34 + b2 + c;
                ai += Gex[0 * 544 + gi] + Gex[2176 + 0 * 544 + gi];
                af += Gex[1 * 544 + gi] + Gex[2176 + 1 * 544 + gi];
                ag += Gex[2 * 544 + gi] + Gex[2176 + 2 * 544 + gi];
                ao += Gex[3 * 544 + gi] + Gex[2176 + 3 * 544 + gi];
            }
            cst[c] = fsig(af) * cst[c] + fsig(ai) * ftanh(ag);
            float h = fsig(ao) * ftanh(cst[c]);
            __half h0 = __float2half(h);
            __half h1 = __float2half(h - __half2float(h0));
            __half* hd = &g_h2[dir][t][0][b0 + b2 + c][u0 + ut];
            hd[0]       = h0;
            hd[B_ * H_] = h1;
            // fp32 transposed copy for MLP
            g_hT[dir][(t * H_ + u0 + ut) * B_ + b0 + b2 + c] = h;
        }

        // release: h visible, then publish flag
        __threadfence();
        __syncthreads();
        if (tid == 0)
            *(volatile unsigned*)&g_flagx[dir][btile][utile][0] = (unsigned)(ts + 1);
    }
}

// ---------------- Kernel C: MLP emissions (fp32 transposed h) ------------
__global__ void mlp_kernel(const float* __restrict__ mlpW,
                           const float* __restrict__ mlpb) {
    __shared__ float Wsm[T_ * 2 * H_];
    for (int i = threadIdx.x; i < T_ * 2 * H_; i += 128) Wsm[i] = mlpW[i];
    __syncthreads();

    int s = blockIdx.x;
    int b = threadIdx.x;

    float acc[T_];
#pragma unroll
    for (int t = 0; t < T_; t++) acc[t] = 0.f;

    const float* hf = &g_hT[0][(s * H_) * B_ + b];
    const float* hb = &g_hT[1][(s * H_) * B_ + b];
#pragma unroll 4
    for (int k = 0; k < H_; k++) {
        float v1 = hf[k * B_];
        float v2 = hb[k * B_];
#pragma unroll
        for (int t = 0; t < T_; t++) {
            acc[t] += v1 * Wsm[t * 512 + k];
            acc[t] += v2 * Wsm[t * 512 + 256 + k];
        }
    }
#pragma unroll
    for (int t = 0; t < T_; t++)
        g_em[(b * S_ + s) * T_ + t] = acc[t] + mlpb[t];
}

// ---------------- Kernel D: CRF Viterbi (one warp per batch) -------------
__global__ void viterbi_kernel(const int* __restrict__ data,
                               const float* __restrict__ stt,
                               const float* __restrict__ trn,
                               const float* __restrict__ ett,
                               float* __restrict__ out) {
    __shared__ int sbp[2][S_][10];
    int w = threadIdx.x >> 5, lane = threadIdx.x & 31;
    int b = blockIdx.x * 2 + w;
    int cc = lane < T_ ? lane : (T_ - 1);

    int cnt = 0;
    for (int s = lane; s < S_; s += 32) cnt += (data[b * S_ + s] != 0);
    for (int off = 16; off; off >>= 1) cnt += __shfl_xor_sync(0xFFFFFFFFu, cnt, off);
    int len = cnt;

    float tr[T_];
#pragma unroll
    for (int p = 0; p < T_; p++) tr[p] = trn[p * T_ + cc];

    float score = stt[cc] + g_em[(b * S_ + 0) * T_ + cc];
    float e_next = g_em[(b * S_ + 1) * T_ + cc];

    for (int t = 1; t < S_; t++) {
        float e = e_next;
        if (t + 1 < S_) e_next = g_em[(b * S_ + t + 1) * T_ + cc];
        float best = -1e30f; int bp = 0;
#pragma unroll
        for (int p = 0; p < T_; p++) {
            float sp = __shfl_sync(0xFFFFFFFFu, score, p);
            float cand = sp + tr[p] + e;
            if (cand > best) { best = cand; bp = p; }   // first-max tie-break
        }
        if (lane < T_) sbp[w][t][lane] = bp;
        if (t < len) score = best;
    }

    float fin = score + ett[cc];
    float bestf = -1e30f; int tag = 0;
#pragma unroll
    for (int p = 0; p < T_; p++) {
        float v = __shfl_sync(0xFFFFFFFFu, fin, p);
        if (v > bestf) { bestf = v; tag = p; }
    }
    if (lane == 0) out[B_ * S_ + b] = bestf;

    if (lane == 0) out[b * S_ + (S_ - 1)] = ((S_ - 1) < len) ? (float)tag : 0.f;
    for (int s2 = S_ - 2; s2 >= 0; s2--) {
        int bpv = sbp[w][s2 + 1][cc];
        int prev = __shfl_sync(0xFFFFFFFFu, bpv, tag);
        if (s2 + 1 < len) tag = prev;
        if (lane == 0) out[b * S_ + s2] = (s2 < len) ? (float)tag : 0.f;
    }
}

// ---------------- launch ----------------
extern "C" void kernel_launch(void* const* d_in, const int* in_sizes, int n_in,
                              void* d_out, int out_size) {
    const int*   data = (const int*)d_in[0];
    // d_in[1] = mask (ignored; mask == (data != 0))
    const float* emb  = (const float*)d_in[2];
    const float* Wihf = (const float*)d_in[3];
    const float* Whhf = (const float*)d_in[4];
    const float* bf   = (const float*)d_in[5];
    const float* Wihb = (const float*)d_in[6];
    const float* Whhb = (const float*)d_in[7];
    const float* bb   = (const float*)d_in[8];
    const float* mlpW = (const float*)d_in[9];
    const float* mlpb = (const float*)d_in[10];
    const float* stt  = (const float*)d_in[11];
    const float* trn  = (const float*)d_in[12];
    const float* ett  = (const float*)d_in[13];
    float* out = (float*)d_out;

    cudaFuncSetAttribute(vocab_kernel, cudaFuncAttributeMaxDynamicSharedMemorySize, 67200);
    cudaFuncSetAttribute(lstm_kernel,  cudaFuncAttributeMaxDynamicSharedMemorySize, 51200);

    reset_kernel<<<8, 512>>>();
    dim3 gV(188, 16);
    vocab_kernel<<<gV, 256, 67200>>>(emb, Wihf, bf, Wihb, bb);
    lstm_kernel<<<128, 256, 51200>>>(Whhf, Whhb, data);
    mlp_kernel<<<512, 128>>>(mlpW, mlpb);
    viterbi_kernel<<<64, 64>>>(data, stt, trn, ett, out);
}

// round 15
// speedup vs baseline: 4.3234x; 1.0315x over previous
#include <cuda_runtime.h>
#include <cuda_bf16.h>
#include <cuda_fp16.h>
#include <cstdint>

// Problem dims
#define S_ 512
#define B_ 128
#define E_ 100
#define H_ 256
#define T_ 9
#define G_ 1024   // 4*H
#define V_ 6000
#define VPAD 6016

// ---------------- scratch (device globals; no allocations) ----------------
__device__ float g_tab[2][VPAD * G_];            // vocab projection table (+bias)
__device__ __half g_h2[2][S_][2][B_][H_];        // h 2-plane fp16 split (MMA B operand)
__device__ float g_hT[2][S_ * H_ * B_];          // fp32 h transposed [s][u][b] (for MLP)
__device__ float g_em[B_ * S_ * T_];             // emissions [b][s][t]
__device__ unsigned g_flagx[2][4][16][32];       // flags [dir][btile][utile], own 128B line

__device__ __forceinline__ float fsig(float x) {
    return __fdividef(1.f, 1.f + __expf(-x));
}
__device__ __forceinline__ float ftanh(float x) {
    return __fdividef(2.f, 1.f + __expf(-2.f * x)) - 1.f;
}

__device__ __forceinline__ uint32_t smem_u32(const void* p) {
    uint32_t a;
    asm("{ .reg .u64 t; cvta.to.shared.u64 t, %1; cvt.u32.u64 %0, t; }"
        : "=r"(a) : "l"(p));
    return a;
}

#define LDMX4(r, addr) \
    asm volatile("ldmatrix.sync.aligned.m8n8.x4.shared.b16 {%0,%1,%2,%3}, [%4];" \
        : "=r"((r)[0]), "=r"((r)[1]), "=r"((r)[2]), "=r"((r)[3]) : "r"(addr))

__device__ __forceinline__ void mma16816h(float* d, const uint32_t* a, const uint32_t* b) {
    asm volatile(
        "mma.sync.aligned.m16n8k16.row.col.f32.f16.f16.f32 "
        "{%0,%1,%2,%3}, {%4,%5,%6,%7}, {%8,%9}, {%0,%1,%2,%3};"
        : "+f"(d[0]), "+f"(d[1]), "+f"(d[2]), "+f"(d[3])
        : "r"(a[0]), "r"(a[1]), "r"(a[2]), "r"(a[3]), "r"(b[0]), "r"(b[1]));
}

__global__ void reset_kernel() {
    int i = blockIdx.x * blockDim.x + threadIdx.x;
    if (i < 2 * 4 * 16 * 32) ((unsigned*)g_flagx)[i] = 0u;
}

// ---------------- Kernel A: VOCAB projection (per-direction launch) ------
__global__ void vocab_kernel(const float* __restrict__ emb,
                             const float* __restrict__ W,
                             const float* __restrict__ bias,
                             int dir) {
    extern __shared__ float sm[];
    float* Xsm = sm;          // [100][36]
    float* Wsm = sm + 3600;   // [100][132]

    int tt = blockIdx.x;
    int g0 = blockIdx.y * 128;

    for (int idx = threadIdx.x; idx < 32 * E_; idx += 256) {
        int j = idx / E_, k = idx - j * E_;
        int v = tt * 32 + j;
        int row = (v < V_) ? v : 0;
        Xsm[k * 36 + j] = emb[row * E_ + k];
    }
    for (int idx = threadIdx.x; idx < 128 * E_; idx += 256) {
        int r = idx / E_, k = idx - r * E_;
        Wsm[k * 132 + r] = W[(g0 + r) * E_ + k];
    }
    __syncthreads();

    int gg = threadIdx.x & 31;
    int tg = threadIdx.x >> 5;
    float acc[4][4];
#pragma unroll
    for (int i = 0; i < 4; i++)
#pragma unroll
        for (int j = 0; j < 4; j++) acc[i][j] = 0.f;

    const float* wp = &Wsm[gg * 4];
    const float* xp = &Xsm[tg * 4];
    for (int k = 0; k < E_; k++) {
        float4 w = *(const float4*)(wp + k * 132);
        float4 x = *(const float4*)(xp + k * 36);
        acc[0][0] += w.x * x.x; acc[0][1] += w.x * x.y; acc[0][2] += w.x * x.z; acc[0][3] += w.x * x.w;
        acc[1][0] += w.y * x.x; acc[1][1] += w.y * x.y; acc[1][2] += w.y * x.z; acc[1][3] += w.y * x.w;
        acc[2][0] += w.z * x.x; acc[2][1] += w.z * x.y; acc[2][2] += w.z * x.z; acc[2][3] += w.z * x.w;
        acc[3][0] += w.w * x.x; acc[3][1] += w.w * x.y; acc[3][2] += w.w * x.z; acc[3][3] += w.w * x.w;
    }

    float b0v = bias[g0 + gg * 4 + 0];
    float b1v = bias[g0 + gg * 4 + 1];
    float b2v = bias[g0 + gg * 4 + 2];
    float b3v = bias[g0 + gg * 4 + 3];
#pragma unroll
    for (int ti = 0; ti < 4; ti++) {
        int v = tt * 32 + tg * 4 + ti;
        if (v < V_) {
            float4 o = make_float4(acc[0][ti] + b0v, acc[1][ti] + b1v,
                                   acc[2][ti] + b2v, acc[3][ti] + b3v);
            *(float4*)&g_tab[dir][v * G_ + g0 + gg * 4] = o;
        }
    }
}

// ---------------- Kernel B: HMMA LSTM, 2-plane fp16 split (3 products) ---
// Identical machinery to R14 (PASSED, rel_err 1.1e-7), but
// __launch_bounds__(256,2): two CTAs co-resident per SM so a second
// (other-direction) CTA fills the flag/L2/ldmatrix latency bubbles.
// SMEM: Bsm 2x[32][264]fp16 @0 (33792B) | Gex [2][4][16][34]f32 @33792
// (17408B). Total 51200 (2x51200 <= 228KB).
__global__ void __launch_bounds__(256, 2)
lstm_kernel(const float* __restrict__ Whhf, const float* __restrict__ Whhb,
            const int* __restrict__ data) {
    extern __shared__ char sp[];
    uint32_t sbase = smem_u32(sp);
    const int off_G = 33792;
    float* Gex = (float*)(sp + off_G);   // [kh 2][gate 4][u 16][b 34]

    int bx    = blockIdx.x;
    int dir   = bx >> 6;
    int cid   = bx & 63;
    int btile = cid & 3;
    int utile = cid >> 2;
    int b0 = btile * 32, u0 = utile * 16;
    const float* Whh = dir ? Whhb : Whhf;

    int tid = threadIdx.x, w = tid >> 5, lane = tid & 31;
    int mt = w & 3;     // gate (m-tile)
    int kh = w >> 2;    // k-half (0..1), 128 k each

    // ldmatrix lane addresses (pitch 528B = 264 halfs)
    uint32_t a_lane = sbase + (uint32_t)((mt * 16 + (lane & 15)) * 528 + (lane >> 4) * 16);
    uint32_t b_lane = sbase + (uint32_t)(((((lane >> 4) & 1) * 8 + (lane & 7)) * 528) + ((lane >> 3) & 1) * 16);
    uint32_t khoff = (uint32_t)(kh * 256);

    uint32_t af0[8][4], af1[8][4];

    // ---- one-time A fragment load: two fp16 planes ----
    {
        __half* Asm = (__half*)sp;
#pragma unroll 1
        for (int p = 0; p < 2; p++) {
            for (int idx = tid; idx < 64 * 256; idx += 256) {
                int r = idx >> 8, k = idx & 255;
                int gate = r >> 4, ul = r & 15;
                float wv = Whh[(gate * 256 + u0 + ul) * 256 + k];
                __half o;
                if (p == 0) o = __float2half(wv);
                else {
                    float w0 = __half2float(__float2half(wv));
                    o = __float2half(wv - w0);
                }
                Asm[r * 264 + k] = o;
            }
            __syncthreads();
            if (p == 0) {
#pragma unroll
                for (int kt = 0; kt < 8; kt++) LDMX4(af0[kt], a_lane + khoff + kt * 32);
            } else {
#pragma unroll
                for (int kt = 0; kt < 8; kt++) LDMX4(af1[kt], a_lane + khoff + kt * 32);
            }
            __syncthreads();
        }
    }

    // epilogue cell assignment: thread = (unit ut, batches b2, b2+1)
    int ut = tid >> 4;
    int b2 = (tid & 15) * 2;
    float cst[2] = {0.f, 0.f};
    const float* tab = g_tab[dir];

    for (int ts = 0; ts < S_; ts++) {
        int t = dir ? (S_ - 1 - ts) : ts;

        // prefetch xg from the vocab table (independent of flag-gated h)
        int tokA = data[(b0 + b2) * S_ + t];
        int tokB = data[(b0 + b2 + 1) * S_ + t];
        float xv[2][4];
        {
            const float* xa = &tab[tokA * G_ + u0 + ut];
            const float* xb = &tab[tokB * G_ + u0 + ut];
#pragma unroll
            for (int g = 0; g < 4; g++) { xv[0][g] = xa[g * 256]; xv[1][g] = xb[g * 256]; }
        }

        if (ts > 0) {
            // wait for the 16 CTAs of this (dir,btile) group: step ts-1 done
            if (tid < 16) {
                volatile unsigned* fr = &g_flagx[dir][btile][tid][0];
                unsigned v;
                do { v = *fr; } while (!__all_sync(0xFFFFu, v >= (unsigned)ts));
                __threadfence();
            }
            __syncthreads();

            // stage B = h(prev) 2 planes [32 b][256 k] -> pitch 264 fp16
            int tp = dir ? (t + 1) : (t - 1);
            const __half* hbase = &g_h2[dir][tp][0][b0][0];
#pragma unroll
            for (int it = 0; it < 8; it++) {
                int idx = tid + it * 256;       // 0..2047 uint4 moves
                int r = idx >> 5, q = idx & 31; // r: plane*32+batch, q: 8-half chunk
                int p = r >> 5, bI = r & 31;
                uint4 v = *(const uint4*)(hbase + p * (B_ * H_) + bI * H_ + q * 8);
                *(uint4*)(sp + p * 16896 + bI * 528 + q * 16) = v;
            }
            __syncthreads();

            float dacc[4][4];
#pragma unroll
            for (int j = 0; j < 4; j++)
#pragma unroll
                for (int q = 0; q < 4; q++) dacc[j][q] = 0.f;

#pragma unroll
            for (int kt = 0; kt < 8; kt++) {
                uint32_t kb = khoff + kt * 32;
                uint32_t q0[8], q1[8];
                LDMX4(q0,     b_lane + kb);
                LDMX4(q0 + 4, b_lane + 8448 + kb);
                LDMX4(q1,     b_lane + 16896 + kb);
                LDMX4(q1 + 4, b_lane + 16896 + 8448 + kb);
#pragma unroll
                for (int j = 0; j < 4; j++) {
                    const uint32_t* b0p = q0 + (j >> 1) * 4 + (j & 1) * 2;
                    const uint32_t* b1p = q1 + (j >> 1) * 4 + (j & 1) * 2;
                    mma16816h(dacc[j], af0[kt], b0p);   // a0 b0
                    mma16816h(dacc[j], af1[kt], b0p);   // a1 b0
                    mma16816h(dacc[j], af0[kt], b1p);   // a0 b1
                }
            }

            // Gex partial-sum exchange: [kh][gate][unit][batch]
            {
                float* gbase = &Gex[kh * 2176 + mt * 544];
                int r0 = lane >> 2;
                int c0 = (lane & 3) * 2;
#pragma unroll
                for (int j = 0; j < 4; j++) {
                    int cb = j * 8 + c0;
                    *(float2*)&gbase[r0 * 34 + cb]       = make_float2(dacc[j][0], dacc[j][1]);
                    *(float2*)&gbase[(r0 + 8) * 34 + cb] = make_float2(dacc[j][2], dacc[j][3]);
                }
            }
            __syncthreads();
        }

        // ---- epilogue: 2 cells per thread ----
#pragma unroll
        for (int c = 0; c < 2; c++) {
            float ai = xv[c][0], af = xv[c][1], ag = xv[c][2], ao = xv[c][3];
            if (ts > 0) {
                int gi = ut * 34 + b2 + c;
                ai += Gex[0 * 544 + gi] + Gex[2176 + 0 * 544 + gi];
                af += Gex[1 * 544 + gi] + Gex[2176 + 1 * 544 + gi];
                ag += Gex[2 * 544 + gi] + Gex[2176 + 2 * 544 + gi];
                ao += Gex[3 * 544 + gi] + Gex[2176 + 3 * 544 + gi];
            }
            cst[c] = fsig(af) * cst[c] + fsig(ai) * ftanh(ag);
            float h = fsig(ao) * ftanh(cst[c]);
            __half h0 = __float2half(h);
            __half h1 = __float2half(h - __half2float(h0));
            __half* hd = &g_h2[dir][t][0][b0 + b2 + c][u0 + ut];
            hd[0]       = h0;
            hd[B_ * H_] = h1;
            // fp32 transposed copy for MLP
            g_hT[dir][(t * H_ + u0 + ut) * B_ + b0 + b2 + c] = h;
        }

        // release: h visible, then publish flag
        __threadfence();
        __syncthreads();
        if (tid == 0)
            *(volatile unsigned*)&g_flagx[dir][btile][utile][0] = (unsigned)(ts + 1);
    }
}

// ---------------- Kernel C: MLP emissions (fp32 transposed h) ------------
__global__ void mlp_kernel(const float* __restrict__ mlpW,
                           const float* __restrict__ mlpb) {
    __shared__ float Wsm[T_ * 2 * H_];
    for (int i = threadIdx.x; i < T_ * 2 * H_; i += 128) Wsm[i] = mlpW[i];
    __syncthreads();

    int s = blockIdx.x;
    int b = threadIdx.x;

    float acc[T_];
#pragma unroll
    for (int t = 0; t < T_; t++) acc[t] = 0.f;

    const float* hf = &g_hT[0][(s * H_) * B_ + b];
    const float* hb = &g_hT[1][(s * H_) * B_ + b];
#pragma unroll 4
    for (int k = 0; k < H_; k++) {
        float v1 = hf[k * B_];
        float v2 = hb[k * B_];
#pragma unroll
        for (int t = 0; t < T_; t++) {
            acc[t] += v1 * Wsm[t * 512 + k];
            acc[t] += v2 * Wsm[t * 512 + 256 + k];
        }
    }
#pragma unroll
    for (int t = 0; t < T_; t++)
        g_em[(b * S_ + s) * T_ + t] = acc[t] + mlpb[t];
}

// ---------------- Kernel D: CRF Viterbi (one warp per batch) -------------
__global__ void viterbi_kernel(const int* __restrict__ data,
                               const float* __restrict__ stt,
                               const float* __restrict__ trn,
                               const float* __restrict__ ett,
                               float* __restrict__ out) {
    __shared__ int sbp[2][S_][10];
    int w = threadIdx.x >> 5, lane = threadIdx.x & 31;
    int b = blockIdx.x * 2 + w;
    int cc = lane < T_ ? lane : (T_ - 1);

    int cnt = 0;
    for (int s = lane; s < S_; s += 32) cnt += (data[b * S_ + s] != 0);
    for (int off = 16; off; off >>= 1) cnt += __shfl_xor_sync(0xFFFFFFFFu, cnt, off);
    int len = cnt;

    float tr[T_];
#pragma unroll
    for (int p = 0; p < T_; p++) tr[p] = trn[p * T_ + cc];

    float score = stt[cc] + g_em[(b * S_ + 0) * T_ + cc];
    float e_next = g_em[(b * S_ + 1) * T_ + cc];

    for (int t = 1; t < S_; t++) {
        float e = e_next;
        if (t + 1 < S_) e_next = g_em[(b * S_ + t + 1) * T_ + cc];
        float best = -1e30f; int bp = 0;
#pragma unroll
        for (int p = 0; p < T_; p++) {
            float sp = __shfl_sync(0xFFFFFFFFu, score, p);
            float cand = sp + tr[p] + e;
            if (cand > best) { best = cand; bp = p; }   // first-max tie-break
        }
        if (lane < T_) sbp[w][t][lane] = bp;
        if (t < len) score = best;
    }

    float fin = score + ett[cc];
    float bestf = -1e30f; int tag = 0;
#pragma unroll
    for (int p = 0; p < T_; p++) {
        float v = __shfl_sync(0xFFFFFFFFu, fin, p);
        if (v > bestf) { bestf = v; tag = p; }
    }
    if (lane == 0) out[B_ * S_ + b] = bestf;

    if (lane == 0) out[b * S_ + (S_ - 1)] = ((S_ - 1) < len) ? (float)tag : 0.f;
    for (int s2 = S_ - 2; s2 >= 0; s2--) {
        int bpv = sbp[w][s2 + 1][cc];
        int prev = __shfl_sync(0xFFFFFFFFu, bpv, tag);
        if (s2 + 1 < len) tag = prev;
        if (lane == 0) out[b * S_ + s2] = (s2 < len) ? (float)tag : 0.f;
    }
}

// ---------------- launch ----------------
extern "C" void kernel_launch(void* const* d_in, const int* in_sizes, int n_in,
                              void* d_out, int out_size) {
    const int*   data = (const int*)d_in[0];
    // d_in[1] = mask (ignored; mask == (data != 0))
    const float* emb  = (const float*)d_in[2];
    const float* Wihf = (const float*)d_in[3];
    const float* Whhf = (const float*)d_in[4];
    const float* bf   = (const float*)d_in[5];
    const float* Wihb = (const float*)d_in[6];
    const float* Whhb = (const float*)d_in[7];
    const float* bb   = (const float*)d_in[8];
    const float* mlpW = (const float*)d_in[9];
    const float* mlpb = (const float*)d_in[10];
    const float* stt  = (const float*)d_in[11];
    const float* trn  = (const float*)d_in[12];
    const float* ett  = (const float*)d_in[13];
    float* out = (float*)d_out;

    cudaFuncSetAttribute(vocab_kernel, cudaFuncAttributeMaxDynamicSharedMemorySize, 67200);
    cudaFuncSetAttribute(lstm_kernel,  cudaFuncAttributeMaxDynamicSharedMemorySize, 51200);

    reset_kernel<<<8, 512>>>();                                   // #1
    dim3 gV(188, 8);
    vocab_kernel<<<gV, 256, 67200>>>(emb, Wihf, bf, 0);           // #2
    vocab_kernel<<<gV, 256, 67200>>>(emb, Wihb, bb, 1);           // #3
    lstm_kernel<<<128, 256, 51200>>>(Whhf, Whhb, data);           // #4 (ncu slot)
    mlp_kernel<<<512, 128>>>(mlpW, mlpb);                         // #5
    viterbi_kernel<<<64, 64>>>(data, stt, trn, ett, out);         // #6
}